// round 3
// baseline (speedup 1.0000x reference)
#include <cuda_runtime.h>
#include <math.h>
#include <stdint.h>

#define BB 8
#define CIN 64
#define COUT 128
#define NPTS 32768
#define RES 32
#define NVOX (RES*RES*RES)
#define GEPS 1e-5f

// ---------------- scratch (static device globals; no allocation) -------------
__device__ float d_msum[BB*3];
__device__ unsigned d_smaxu[BB];
__device__ float d_normc[BB*3*NPTS];
__device__ float d_grid0[BB*NVOX*CIN];    //  67 MB  [b][v][ci]
__device__ float d_cnt[BB*NVOX];
__device__ float d_grid1[BB*NVOX*COUT];   // 134 MB  [b][v][o]
__device__ float d_grid2[BB*NVOX*COUT];   // 134 MB
__device__ float d_pt[BB*NPTS*COUT];      // 134 MB  [b][n][o]
__device__ float2 d_wtd1[CIN*27*COUT];    // duplicated {w,w}, [(ci*27+t)][o]
__device__ float2 d_wtd2[COUT*27*COUT];
__device__ float d_ptw[CIN*COUT];         // [ci][o]
__device__ float d_gstats1[BB*8*2];
__device__ float d_cstats2[BB*COUT*2];
__device__ float d_ptstats[BB*8*2];
__device__ float d_A[BB*COUT];
__device__ float d_Bc[BB*COUT];
__device__ float d_ptA[BB*COUT];
__device__ float d_ptB[BB*COUT];

#define FMA2(acc, a, b) asm("fma.rn.f32x2 %0, %1, %2, %0;" : "+l"(acc) : "l"(a), "l"(b))

// ---------------- prep: weight transposes (duplicated for LDG.64 {w,w}) ------
__global__ void k_prep(const float* __restrict__ w1, const float* __restrict__ w2,
                       const float* __restrict__ ptw) {
    int i = blockIdx.x * 256 + threadIdx.x;
    if (i < CIN*27*COUT) {
        int o = i & 127; int r = i >> 7; int ci = r / 27, t = r % 27;
        float w = w1[(o*CIN + ci)*27 + t];
        d_wtd1[i] = make_float2(w, w);
    }
    if (i < COUT*27*COUT) {
        int o = i & 127; int r = i >> 7; int ci = r / 27, t = r % 27;
        float w = w2[(o*COUT + ci)*27 + t];
        d_wtd2[i] = make_float2(w, w);
    }
    if (i < CIN*COUT) {
        int o = i & 127; int ci = i >> 7;
        d_ptw[i] = ptw[o*CIN + ci];
    }
}

__global__ void k_zero() {
    int i = blockIdx.x * 256 + threadIdx.x;   // 16,777,216 threads exactly
    d_grid0[i] = 0.f;
    if (i < BB*NVOX)   d_cnt[i] = 0.f;
    if (i < BB*8*2)    d_gstats1[i] = 0.f;
    if (i < BB*COUT*2) d_cstats2[i] = 0.f;
    if (i < BB*8*2)    d_ptstats[i] = 0.f;
    if (i < BB*3)      d_msum[i] = 0.f;
    if (i < BB)        d_smaxu[i] = 0u;
}

// ---------------- voxelize coords (parallel chunked reductions) --------------
__global__ void k_mean1(const float* __restrict__ coords) {
    int blk = blockIdx.x;                 // BB*3*16
    int chunk = blk & 15; int d = (blk >> 4) % 3; int b = blk / 48;
    __shared__ float s[256];
    float acc = 0.f;
    int base = (b*3 + d)*NPTS + chunk*2048;
    for (int n = threadIdx.x; n < 2048; n += 256) acc += coords[base + n];
    s[threadIdx.x] = acc; __syncthreads();
    for (int o = 128; o > 0; o >>= 1) {
        if (threadIdx.x < o) s[threadIdx.x] += s[threadIdx.x + o];
        __syncthreads();
    }
    if (threadIdx.x == 0) atomicAdd(&d_msum[b*3 + d], s[0]);
}

__global__ void k_scale1(const float* __restrict__ coords) {
    int blk = blockIdx.x;                 // BB*16
    int chunk = blk & 15; int b = blk >> 4;
    float mx = d_msum[b*3]   * (1.f/(float)NPTS);
    float my = d_msum[b*3+1] * (1.f/(float)NPTS);
    float mz = d_msum[b*3+2] * (1.f/(float)NPTS);
    __shared__ float s[256];
    float m = 0.f;
    int n0 = chunk*2048;
    for (int n = threadIdx.x; n < 2048; n += 256) {
        float x = coords[(b*3+0)*NPTS + n0 + n] - mx;
        float y = coords[(b*3+1)*NPTS + n0 + n] - my;
        float z = coords[(b*3+2)*NPTS + n0 + n] - mz;
        m = fmaxf(m, sqrtf(x*x + y*y + z*z));
    }
    s[threadIdx.x] = m; __syncthreads();
    for (int o = 128; o > 0; o >>= 1) {
        if (threadIdx.x < o) s[threadIdx.x] = fmaxf(s[threadIdx.x], s[threadIdx.x + o]);
        __syncthreads();
    }
    if (threadIdx.x == 0) atomicMax(&d_smaxu[b], __float_as_uint(s[0]));
}

__global__ void k_norm(const float* __restrict__ coords) {
    int i = blockIdx.x * 256 + threadIdx.x;
    if (i >= BB*3*NPTS) return;
    int b = i / (3*NPTS); int d = (i / NPTS) % 3;
    float mean = d_msum[b*3 + d] * (1.f/(float)NPTS);
    float scale = __uint_as_float(d_smaxu[b]) * 2.f;
    float t = (coords[i] - mean) / scale + 0.5f;
    d_normc[i] = fminf(fmaxf(t * (float)RES, 0.f), (float)(RES - 1));
}

// ---------------- scatter-mean voxelization ----------------------------------
__global__ void k_scatter(const float* __restrict__ feat) {
    int p = blockIdx.x * 256 + threadIdx.x;
    if (p >= BB*NPTS) return;
    int b = p >> 15, n = p & (NPTS - 1);
    int ix = min(max((int)rintf(d_normc[(b*3+0)*NPTS + n]), 0), RES-1);
    int iy = min(max((int)rintf(d_normc[(b*3+1)*NPTS + n]), 0), RES-1);
    int iz = min(max((int)rintf(d_normc[(b*3+2)*NPTS + n]), 0), RES-1);
    int vid = (ix*RES + iy)*RES + iz;
    float* row = &d_grid0[(long)(b*NVOX + vid) * CIN];
    #pragma unroll 4
    for (int c = 0; c < CIN; c++)
        atomicAdd(&row[c], feat[((long)(b*CIN) + c)*NPTS + n]);
    atomicAdd(&d_cnt[b*NVOX + vid], 1.f);
}

__global__ void k_div() {
    int i = blockIdx.x * 256 + threadIdx.x;   // B*NVOX*CIN threads
    float c = d_cnt[i / CIN];
    d_grid0[i] = d_grid0[i] / fmaxf(c, 1.f);
}

// ---------------- 3x3x3 conv, channels-last, half z-line per block -----------
// Block covers 16 z outputs (zh selects half). 256 thr = 128 o x 2 z-subhalves.
// f32x2 packed FMA: each thread computes 8 z = 4 packed pairs.
// SMEM rows of 20 floats: z inputs [zb-1, zb+17).
template<int CI, int STAGE>
__global__ void __launch_bounds__(256) k_conv(const float* __restrict__ bias) {
    extern __shared__ float sm[];                      // [ci*9+xy][20]
    const float*  __restrict__ gin  = (STAGE == 0) ? d_grid0 : d_grid1;
    float*        __restrict__ gout = (STAGE == 0) ? d_grid1 : d_grid2;
    const float2* __restrict__ wt   = (STAGE == 0) ? d_wtd1  : d_wtd2;

    int blk = blockIdx.x;                               // BB*32*32*2
    int zh = blk & 1, yr = (blk >> 1) & 31, xr = (blk >> 6) & 31, b = blk >> 11;
    int zb = zh * 16;

    const int TOT = CI * 9 * 18;                        // valid stage entries
    for (int e = threadIdx.x; e < TOT; e += 256) {
        int ci = e % CI; int rest = e / CI;
        int zz = rest % 18; int xy = rest / 18;
        int gx = xr - 1 + xy / 3, gy = yr - 1 + xy % 3, gz = zb - 1 + zz;
        float v = 0.f;
        if (gx >= 0 && gx < RES && gy >= 0 && gy < RES && gz >= 0 && gz < RES)
            v = gin[((long)(b*NVOX) + (gx*RES + gy)*RES + gz) * CI + ci];
        sm[(ci*9 + xy)*20 + zz] = v;
    }
    __syncthreads();

    int o = threadIdx.x & 127, h = threadIdx.x >> 7, zloc = h * 8;

    uint64_t A[4];
    {
        float bv = bias[o];
        uint64_t bp; asm("mov.b64 %0, {%1,%1};" : "=l"(bp) : "f"(bv));
        A[0] = bp; A[1] = bp; A[2] = bp; A[3] = bp;
    }

    const int NI = CI * 9;
    // weight prefetch (distance 1); LDG.64 of duplicated {w,w}
    const float2* wp = wt + o;
    float2 wn0 = wp[0], wn1 = wp[COUT], wn2 = wp[2*COUT];

    #pragma unroll 1
    for (int ii = 0; ii < NI; ii++) {
        float2 cw0 = wn0, cw1 = wn1, cw2 = wn2;
        if (ii + 1 < NI) {
            const float2* wq = wt + (ii + 1)*3*COUT + o;
            wn0 = wq[0]; wn1 = wq[COUT]; wn2 = wq[2*COUT];
        }
        // aligned even pairs straight from LDS.64
        union { float2 f2[5]; uint64_t u[5]; } E;
        const float2* ip2 = (const float2*)(sm + ii*20 + zloc);
        #pragma unroll
        for (int j = 0; j < 5; j++) E.f2[j] = ip2[j];
        // odd pairs {in[2j+1], in[2j+2]}
        uint64_t O[4];
        #pragma unroll
        for (int j = 0; j < 4; j++)
            asm("mov.b64 %0, {%1,%2};" : "=l"(O[j]) : "f"(E.f2[j].y), "f"(E.f2[j+1].x));

        uint64_t w0u = *(uint64_t*)&cw0, w1u = *(uint64_t*)&cw1, w2u = *(uint64_t*)&cw2;
        #pragma unroll
        for (int j = 0; j < 4; j++) {
            FMA2(A[j], w0u, E.u[j]);
            FMA2(A[j], w1u, O[j]);
            FMA2(A[j], w2u, E.u[j+1]);
        }
    }

    long base = ((long)(b*NVOX) + (xr*RES + yr)*RES + zb + zloc) * COUT + o;
    #pragma unroll
    for (int j = 0; j < 4; j++) {
        float lo, hi;
        asm("mov.b64 {%0,%1}, %2;" : "=f"(lo), "=f"(hi) : "l"(A[j]));
        gout[base + (long)(2*j)   * COUT] = lo;
        gout[base + (long)(2*j+1) * COUT] = hi;
    }
}

// ---------------- GN1 stats + normalize+swish --------------------------------
__global__ void k_gstats1() {
    int b = blockIdx.x >> 6, ch = blockIdx.x & 63;     // 512 voxels per chunk
    int c = threadIdx.x & 127, l2 = threadIdx.x >> 7;
    long base = ((long)b*NVOX + ch*512) * COUT;
    float s = 0.f, q = 0.f;
    for (int v = l2; v < 512; v += 2) {
        float x = d_grid1[base + (long)v*COUT + c];
        s += x; q += x*x;
    }
    __shared__ float ss[256], sq[256];
    ss[threadIdx.x] = s; sq[threadIdx.x] = q;
    __syncthreads();
    if (threadIdx.x < 8) {
        float S = 0.f, Q = 0.f;
        for (int j = 0; j < 16; j++) {
            int cc = threadIdx.x*16 + j;
            S += ss[cc] + ss[cc+128]; Q += sq[cc] + sq[cc+128];
        }
        atomicAdd(&d_gstats1[(b*8 + threadIdx.x)*2 + 0], S);
        atomicAdd(&d_gstats1[(b*8 + threadIdx.x)*2 + 1], Q);
    }
}

__global__ void k_gn1(const float* __restrict__ g, const float* __restrict__ bt) {
    int i = blockIdx.x * 256 + threadIdx.x;            // B*NVOX*COUT threads
    int c = i & 127; int b = i >> 22;
    int gr = c >> 4;
    float S = d_gstats1[(b*8 + gr)*2], Q = d_gstats1[(b*8 + gr)*2 + 1];
    const float cnt = (float)NVOX * 16.f;
    float mu = S / cnt; float var = Q / cnt - mu*mu;
    float rs = rsqrtf(var + GEPS);
    float y = (d_grid1[i] - mu) * rs * g[c] + bt[c];
    d_grid1[i] = y / (1.f + expf(-y));
}

// ---------------- GN2 per-channel stats (for GN + SE fold) -------------------
__global__ void k_cstats2() {
    int b = blockIdx.x >> 6, ch = blockIdx.x & 63;
    int c = threadIdx.x & 127, l2 = threadIdx.x >> 7;
    long base = ((long)b*NVOX + ch*512) * COUT;
    float s = 0.f, q = 0.f;
    for (int v = l2; v < 512; v += 2) {
        float x = d_grid2[base + (long)v*COUT + c];
        s += x; q += x*x;
    }
    __shared__ float ss[256], sq[256];
    ss[threadIdx.x] = s; sq[threadIdx.x] = q;
    __syncthreads();
    if (threadIdx.x < 128) {
        atomicAdd(&d_cstats2[(b*COUT + c)*2 + 0], ss[c] + ss[c+128]);
        atomicAdd(&d_cstats2[(b*COUT + c)*2 + 1], sq[c] + sq[c+128]);
    }
}

// ---------------- SE + fold GN2*SE into per-(b,c) affine ---------------------
__global__ void k_se(const float* __restrict__ w1, const float* __restrict__ b1,
                     const float* __restrict__ w2, const float* __restrict__ b2,
                     const float* __restrict__ gamma, const float* __restrict__ beta) {
    int b = blockIdx.x; int c = threadIdx.x;
    __shared__ float s[128], gmu[8], grs[8], s1[16];
    const float cnt = (float)NVOX;
    if (c < 8) {
        float S = 0.f, Q = 0.f;
        for (int j = 0; j < 16; j++) {
            S += d_cstats2[(b*COUT + c*16 + j)*2 + 0];
            Q += d_cstats2[(b*COUT + c*16 + j)*2 + 1];
        }
        float gc = cnt * 16.f;
        float mu = S / gc; float var = Q / gc - mu*mu;
        gmu[c] = mu; grs[c] = rsqrtf(var + GEPS);
    }
    __syncthreads();
    int gr = c >> 4;
    float mu = gmu[gr], rs = grs[gr];
    float csum = d_cstats2[(b*COUT + c)*2];
    s[c] = (csum / cnt - mu) * rs * gamma[c] + beta[c];
    __syncthreads();
    if (c < 16) {
        float a = b1[c];
        for (int j = 0; j < 128; j++) a += w1[c*128 + j] * s[j];
        s1[c] = fmaxf(a, 0.f);
    }
    __syncthreads();
    float a2 = b2[c];
    for (int j = 0; j < 16; j++) a2 += w2[c*16 + j] * s1[j];
    float se = 1.f / (1.f + expf(-a2));
    float rg = rs * gamma[c];
    d_A [b*COUT + c] = rg * se;
    d_Bc[b*COUT + c] = (beta[c] - mu * rg) * se;
}

// ---------------- point branch 1x1 conv + stats ------------------------------
__global__ void k_pt(const float* __restrict__ feat, const float* __restrict__ ptb) {
    int blk = blockIdx.x;
    int b = blk >> 10, n0 = (blk & 1023) * 32;
    __shared__ float fs[CIN*32];       // [ci][nn]
    __shared__ float so[32*COUT];      // [nn][o]
    __shared__ float ss[256], sq[256];
    for (int e = threadIdx.x; e < CIN*32; e += 256) {
        int ci = e >> 5, nn = e & 31;
        fs[e] = feat[((long)(b*CIN) + ci)*NPTS + n0 + nn];
    }
    __syncthreads();
    int o = threadIdx.x & 127, h = threadIdx.x >> 7;
    float acc[16];
    float bv = ptb[o];
    #pragma unroll
    for (int j = 0; j < 16; j++) acc[j] = bv;
    for (int ci = 0; ci < CIN; ci++) {
        float w = d_ptw[ci*COUT + o];
        #pragma unroll
        for (int j = 0; j < 16; j++)
            acc[j] = fmaf(w, fs[ci*32 + h*16 + j], acc[j]);
    }
    float s = 0.f, q = 0.f;
    #pragma unroll
    for (int j = 0; j < 16; j++) {
        s += acc[j]; q += acc[j]*acc[j];
        so[(h*16 + j)*COUT + o] = acc[j];
    }
    ss[threadIdx.x] = s; sq[threadIdx.x] = q;
    __syncthreads();
    if (threadIdx.x < 8) {
        float S = 0.f, Q = 0.f;
        for (int j = 0; j < 16; j++) {
            int cc = threadIdx.x*16 + j;
            S += ss[cc] + ss[cc+128]; Q += sq[cc] + sq[cc+128];
        }
        atomicAdd(&d_ptstats[(b*8 + threadIdx.x)*2 + 0], S);
        atomicAdd(&d_ptstats[(b*8 + threadIdx.x)*2 + 1], Q);
    }
    for (int e = threadIdx.x; e < 32*COUT; e += 256) {
        int nn = e >> 7, oo = e & 127;
        d_pt[((long)(b*NPTS) + n0 + nn)*COUT + oo] = so[e];
    }
}

__global__ void k_ptab(const float* __restrict__ g, const float* __restrict__ bt) {
    int i = blockIdx.x * 256 + threadIdx.x;
    if (i >= BB*COUT) return;
    int b = i >> 7, c = i & 127, gr = c >> 4;
    const float cnt = 16.f * (float)NPTS;
    float S = d_ptstats[(b*8 + gr)*2], Q = d_ptstats[(b*8 + gr)*2 + 1];
    float mu = S / cnt, var = Q / cnt - mu*mu, rs = rsqrtf(var + GEPS);
    d_ptA[i] = rs * g[c];
    d_ptB[i] = bt[c] - mu * rs * g[c];
}

// ---------------- trilinear devoxelize + point add -> out --------------------
__global__ void k_out(float* __restrict__ out) {
    int p = blockIdx.x * 4 + (threadIdx.x >> 5);
    int lane = threadIdx.x & 31;
    int b = p >> 15, n = p & (NPTS - 1);
    float nx = d_normc[(b*3+0)*NPTS + n];
    float ny = d_normc[(b*3+1)*NPTS + n];
    float nz = d_normc[(b*3+2)*NPTS + n];
    int lx = (int)floorf(nx); float fx = nx - (float)lx; int hx = min(lx+1, RES-1);
    int ly = (int)floorf(ny); float fy = ny - (float)ly; int hy = min(ly+1, RES-1);
    int lz = (int)floorf(nz); float fz = nz - (float)lz; int hz = min(lz+1, RES-1);

    float4 acc = make_float4(0.f, 0.f, 0.f, 0.f);
    float sumw = 0.f;
    const float4* gp = (const float4*)d_grid2;
    #pragma unroll
    for (int k = 0; k < 8; k++) {
        int dx = k >> 2, dy = (k >> 1) & 1, dz = k & 1;
        int ix = dx ? hx : lx, iy = dy ? hy : ly, iz = dz ? hz : lz;
        float w = (dx ? fx : 1.f - fx) * (dy ? fy : 1.f - fy) * (dz ? fz : 1.f - fz);
        long row = ((long)(b*NVOX) + (ix*RES + iy)*RES + iz) * (COUT/4);
        float4 v = gp[row + lane];
        acc.x += w*v.x; acc.y += w*v.y; acc.z += w*v.z; acc.w += w*v.w;
        sumw += w;
    }
    float4 a  = ((const float4*)d_A )[b*32 + lane];
    float4 bc = ((const float4*)d_Bc)[b*32 + lane];
    float4 gv;
    gv.x = acc.x*a.x + sumw*bc.x; gv.y = acc.y*a.y + sumw*bc.y;
    gv.z = acc.z*a.z + sumw*bc.z; gv.w = acc.w*a.w + sumw*bc.w;

    float4 pv = ((const float4*)d_pt)[((long)(b*NPTS) + n)*32 + lane];
    float4 pa = ((const float4*)d_ptA)[b*32 + lane];
    float4 pb = ((const float4*)d_ptB)[b*32 + lane];
    float y;
    y = pv.x*pa.x + pb.x; gv.x += y / (1.f + expf(-y));
    y = pv.y*pa.y + pb.y; gv.y += y / (1.f + expf(-y));
    y = pv.z*pa.z + pb.z; gv.z += y / (1.f + expf(-y));
    y = pv.w*pa.w + pb.w; gv.w += y / (1.f + expf(-y));

    long ob = ((long)(b*COUT) + lane*4) * NPTS + n;
    out[ob]          = gv.x;
    out[ob + NPTS]   = gv.y;
    out[ob + 2*NPTS] = gv.z;
    out[ob + 3*NPTS] = gv.w;
}

// ---------------- launch ------------------------------------------------------
extern "C" void kernel_launch(void* const* d_in, const int* in_sizes, int n_in,
                              void* d_out, int out_size) {
    const float* features = (const float*)d_in[0];
    const float* coords   = (const float*)d_in[1];
    const float* conv1_w  = (const float*)d_in[2];
    const float* conv1_b  = (const float*)d_in[3];
    const float* gn1_g    = (const float*)d_in[4];
    const float* gn1_b    = (const float*)d_in[5];
    const float* conv2_w  = (const float*)d_in[6];
    const float* conv2_b  = (const float*)d_in[7];
    const float* gn2_g    = (const float*)d_in[8];
    const float* gn2_b    = (const float*)d_in[9];
    const float* se_w1    = (const float*)d_in[10];
    const float* se_b1    = (const float*)d_in[11];
    const float* se_w2    = (const float*)d_in[12];
    const float* se_b2    = (const float*)d_in[13];
    const float* pt_w     = (const float*)d_in[14];
    const float* pt_b     = (const float*)d_in[15];
    const float* ptgn_g   = (const float*)d_in[16];
    const float* ptgn_b   = (const float*)d_in[17];
    float* out = (float*)d_out;

    const int SM1 = CIN*9*20*4;    // 46080
    const int SM2 = COUT*9*20*4;   // 92160
    cudaFuncSetAttribute(k_conv<CIN,0>,  cudaFuncAttributeMaxDynamicSharedMemorySize, SM1);
    cudaFuncSetAttribute(k_conv<COUT,1>, cudaFuncAttributeMaxDynamicSharedMemorySize, SM2);

    k_prep<<<(COUT*27*COUT + 255)/256, 256>>>(conv1_w, conv2_w, pt_w);
    k_zero<<<(BB*NVOX*CIN)/256, 256>>>();
    k_mean1<<<BB*3*16, 256>>>(coords);
    k_scale1<<<BB*16, 256>>>(coords);
    k_norm<<<(BB*3*NPTS + 255)/256, 256>>>(coords);
    k_scatter<<<(BB*NPTS + 255)/256, 256>>>(features);
    k_div<<<(BB*NVOX*CIN)/256, 256>>>();
    k_conv<CIN,0><<<BB*RES*RES*2, 256, SM1>>>(conv1_b);
    k_gstats1<<<BB*64, 256>>>();
    k_gn1<<<(BB*NVOX*COUT)/256, 256>>>(gn1_g, gn1_b);
    k_conv<COUT,1><<<BB*RES*RES*2, 256, SM2>>>(conv2_b);
    k_cstats2<<<BB*64, 256>>>();
    k_se<<<BB, 128>>>(se_w1, se_b1, se_w2, se_b2, gn2_g, gn2_b);
    k_pt<<<BB*(NPTS/32), 256>>>(features, pt_b);
    k_ptab<<<(BB*COUT + 255)/256, 256>>>(ptgn_g, ptgn_b);
    k_out<<<(BB*NPTS)/4, 128>>>(out);
}

// round 4
// speedup vs baseline: 1.8189x; 1.8189x over previous
#include <cuda_runtime.h>
#include <math.h>
#include <stdint.h>

#define BB 8
#define CIN 64
#define COUT 128
#define NPTS 32768
#define RES 32
#define NVOX (RES*RES*RES)
#define GEPS 1e-5f

// ---------------- scratch (static device globals; no allocation) -------------
__device__ float d_msum[BB*3];
__device__ unsigned d_smaxu[BB];
__device__ float d_normc[BB*3*NPTS];
__device__ float d_grid0[BB*NVOX*CIN];    //  67 MB  [b][v][ci]
__device__ float d_cnt[BB*NVOX];
__device__ float d_grid1[BB*NVOX*COUT];   // 134 MB  [b][v][o]
__device__ float d_grid2[BB*NVOX*COUT];   // 134 MB
__device__ float d_pt[BB*NPTS*COUT];      // 134 MB  [b][n][o]
__device__ float d_wt1[CIN*27*COUT];      // [(ci*27+t)][o]
__device__ float d_wt2[COUT*27*COUT];
__device__ float d_ptw[CIN*COUT];         // [ci][o]
__device__ float d_gstats1[BB*8*2];
__device__ float d_cstats2[BB*COUT*2];
__device__ float d_ptstats[BB*8*2];
__device__ float d_A[BB*COUT];
__device__ float d_Bc[BB*COUT];
__device__ float d_ptA[BB*COUT];
__device__ float d_ptB[BB*COUT];

// ---------------- prep: weight transposes -----------------------------------
__global__ void k_prep(const float* __restrict__ w1, const float* __restrict__ w2,
                       const float* __restrict__ ptw) {
    int i = blockIdx.x * 256 + threadIdx.x;
    if (i < CIN*27*COUT) {           // wt1[(ci*27+t)*128+o] = w1[(o*CIN+ci)*27+t]
        int o = i & 127; int r = i >> 7; int ci = r / 27, t = r % 27;
        d_wt1[i] = w1[(o*CIN + ci)*27 + t];
    }
    if (i < COUT*27*COUT) {
        int o = i & 127; int r = i >> 7; int ci = r / 27, t = r % 27;
        d_wt2[i] = w2[(o*COUT + ci)*27 + t];
    }
    if (i < CIN*COUT) {
        int o = i & 127; int ci = i >> 7;
        d_ptw[i] = ptw[o*CIN + ci];
    }
}

__global__ void k_zero() {
    int i = blockIdx.x * 256 + threadIdx.x;   // 16,777,216 threads exactly
    d_grid0[i] = 0.f;
    if (i < BB*NVOX)   d_cnt[i] = 0.f;
    if (i < BB*8*2)    d_gstats1[i] = 0.f;
    if (i < BB*COUT*2) d_cstats2[i] = 0.f;
    if (i < BB*8*2)    d_ptstats[i] = 0.f;
    if (i < BB*3)      d_msum[i] = 0.f;
    if (i < BB)        d_smaxu[i] = 0u;
}

// ---------------- voxelize coords (parallel chunked reductions) --------------
__global__ void k_mean1(const float* __restrict__ coords) {
    int blk = blockIdx.x;                 // BB*3*16
    int chunk = blk & 15; int d = (blk >> 4) % 3; int b = blk / 48;
    __shared__ float s[256];
    float acc = 0.f;
    int base = (b*3 + d)*NPTS + chunk*2048;
    for (int n = threadIdx.x; n < 2048; n += 256) acc += coords[base + n];
    s[threadIdx.x] = acc; __syncthreads();
    for (int o = 128; o > 0; o >>= 1) {
        if (threadIdx.x < o) s[threadIdx.x] += s[threadIdx.x + o];
        __syncthreads();
    }
    if (threadIdx.x == 0) atomicAdd(&d_msum[b*3 + d], s[0]);
}

__global__ void k_scale1(const float* __restrict__ coords) {
    int blk = blockIdx.x;                 // BB*16
    int chunk = blk & 15; int b = blk >> 4;
    float mx = d_msum[b*3]   * (1.f/(float)NPTS);
    float my = d_msum[b*3+1] * (1.f/(float)NPTS);
    float mz = d_msum[b*3+2] * (1.f/(float)NPTS);
    __shared__ float s[256];
    float m = 0.f;
    int n0 = chunk*2048;
    for (int n = threadIdx.x; n < 2048; n += 256) {
        float x = coords[(b*3+0)*NPTS + n0 + n] - mx;
        float y = coords[(b*3+1)*NPTS + n0 + n] - my;
        float z = coords[(b*3+2)*NPTS + n0 + n] - mz;
        m = fmaxf(m, sqrtf(x*x + y*y + z*z));
    }
    s[threadIdx.x] = m; __syncthreads();
    for (int o = 128; o > 0; o >>= 1) {
        if (threadIdx.x < o) s[threadIdx.x] = fmaxf(s[threadIdx.x], s[threadIdx.x + o]);
        __syncthreads();
    }
    if (threadIdx.x == 0) atomicMax(&d_smaxu[b], __float_as_uint(s[0]));
}

__global__ void k_norm(const float* __restrict__ coords) {
    int i = blockIdx.x * 256 + threadIdx.x;
    if (i >= BB*3*NPTS) return;
    int b = i / (3*NPTS); int d = (i / NPTS) % 3;
    float mean = d_msum[b*3 + d] * (1.f/(float)NPTS);
    float scale = __uint_as_float(d_smaxu[b]) * 2.f;
    float t = (coords[i] - mean) / scale + 0.5f;
    d_normc[i] = fminf(fmaxf(t * (float)RES, 0.f), (float)(RES - 1));
}

// ---------------- scatter-mean voxelization (warp per point) -----------------
__global__ void k_scatter(const float* __restrict__ feat) {
    int warp = threadIdx.x >> 5, lane = threadIdx.x & 31;
    int p = blockIdx.x * 8 + warp;        // BB*NPTS/8 blocks
    int b = p >> 15, n = p & (NPTS - 1);
    int ix = min(max((int)rintf(d_normc[(b*3+0)*NPTS + n]), 0), RES-1);
    int iy = min(max((int)rintf(d_normc[(b*3+1)*NPTS + n]), 0), RES-1);
    int iz = min(max((int)rintf(d_normc[(b*3+2)*NPTS + n]), 0), RES-1);
    int vid = (ix*RES + iy)*RES + iz;
    const float* frow = feat + (long)b*CIN*NPTS + n;
    float v0 = frow[(long)lane * NPTS];
    float v1 = frow[(long)(lane + 32) * NPTS];
    float* row = &d_grid0[(long)(b*NVOX + vid) * CIN];
    atomicAdd(&row[lane],      v0);
    atomicAdd(&row[lane + 32], v1);
    if (lane == 0) atomicAdd(&d_cnt[b*NVOX + vid], 1.f);
}

__global__ void k_div() {
    int i = blockIdx.x * 256 + threadIdx.x;   // B*NVOX*CIN threads
    float c = d_cnt[i / CIN];
    d_grid0[i] = d_grid0[i] / fmaxf(c, 1.f);
}

// ---------------- 3x3x3 conv, channels-last, z-line per block ----------------
// ci chunked by 32: smem buffer [32ci][9xy][36z] = 41.5KB -> ~3 blocks/SM.
// 256 thr = 128 o x 2 z-halves of 16. Weight LDGs prefetched distance-1.
template<int CI, int STAGE>
__global__ void __launch_bounds__(256) k_conv(const float* __restrict__ bias) {
    __shared__ float sm[32*9*36];
    const float* __restrict__ gin  = (STAGE == 0) ? d_grid0 : d_grid1;
    float*       __restrict__ gout = (STAGE == 0) ? d_grid1 : d_grid2;
    const float* __restrict__ wt   = (STAGE == 0) ? d_wt1   : d_wt2;

    int blk = blockIdx.x;
    int b = blk >> 10, xr = (blk >> 5) & 31, yr = blk & 31;
    int o = threadIdx.x & 127, h = threadIdx.x >> 7, z0h = h * 16;

    float acc[16];
    float bv = bias[o];
    #pragma unroll
    for (int z = 0; z < 16; z++) acc[z] = bv;

    const int CHUNKS = CI / 32;
    for (int ck = 0; ck < CHUNKS; ck++) {
        if (ck) __syncthreads();
        // stage 32 channels: 32*9*34 = 9792 elements
        for (int e = threadIdx.x; e < 32*9*34; e += 256) {
            int ci = e & 31; int rest = e >> 5;
            int zz = rest % 34; int xy = rest / 34;
            int gx = xr - 1 + xy / 3, gy = yr - 1 + xy % 3, gz = zz - 1;
            float v = 0.f;
            if (gx >= 0 && gx < RES && gy >= 0 && gy < RES && gz >= 0 && gz < RES)
                v = gin[((long)(b*NVOX) + (gx*RES + gy)*RES + gz) * CI + ck*32 + ci];
            sm[(ci*9 + xy)*36 + zz] = v;
        }
        __syncthreads();

        const float* wbase = wt + (long)(ck*288) * 3 * COUT + o;
        float wn0 = wbase[0], wn1 = wbase[COUT], wn2 = wbase[2*COUT];

        #pragma unroll 1
        for (int ii = 0; ii < 288; ii++) {
            float cw0 = wn0, cw1 = wn1, cw2 = wn2;
            if (ii + 1 < 288) {
                const float* wq = wbase + (ii + 1) * 3 * COUT;
                wn0 = wq[0]; wn1 = wq[COUT]; wn2 = wq[2*COUT];
            }
            float4 v4[5];
            const float4* ip4 = (const float4*)(sm + ii*36 + z0h);
            #pragma unroll
            for (int j = 0; j < 5; j++) v4[j] = ip4[j];
            const float* inr = (const float*)v4;
            #pragma unroll
            for (int z = 0; z < 16; z++) {
                float a = acc[z];
                a = fmaf(cw0, inr[z],     a);
                a = fmaf(cw1, inr[z + 1], a);
                a = fmaf(cw2, inr[z + 2], a);
                acc[z] = a;
            }
        }
    }

    long base = ((long)(b*NVOX) + (xr*RES + yr)*RES + z0h) * COUT + o;
    #pragma unroll
    for (int z = 0; z < 16; z++) gout[base + (long)z * COUT] = acc[z];
}

// ---------------- GN1 stats + normalize+swish --------------------------------
__global__ void k_gstats1() {
    int b = blockIdx.x >> 6, ch = blockIdx.x & 63;     // 512 voxels per chunk
    int c = threadIdx.x & 127, l2 = threadIdx.x >> 7;
    long base = ((long)b*NVOX + ch*512) * COUT;
    float s = 0.f, q = 0.f;
    for (int v = l2; v < 512; v += 2) {
        float x = d_grid1[base + (long)v*COUT + c];
        s += x; q += x*x;
    }
    __shared__ float ss[256], sq[256];
    ss[threadIdx.x] = s; sq[threadIdx.x] = q;
    __syncthreads();
    if (threadIdx.x < 8) {
        float S = 0.f, Q = 0.f;
        for (int j = 0; j < 16; j++) {
            int cc = threadIdx.x*16 + j;
            S += ss[cc] + ss[cc+128]; Q += sq[cc] + sq[cc+128];
        }
        atomicAdd(&d_gstats1[(b*8 + threadIdx.x)*2 + 0], S);
        atomicAdd(&d_gstats1[(b*8 + threadIdx.x)*2 + 1], Q);
    }
}

__global__ void k_gn1(const float* __restrict__ g, const float* __restrict__ bt) {
    int i = blockIdx.x * 256 + threadIdx.x;            // B*NVOX*COUT threads
    int c = i & 127; int b = i >> 22;
    int gr = c >> 4;
    float S = d_gstats1[(b*8 + gr)*2], Q = d_gstats1[(b*8 + gr)*2 + 1];
    const float cnt = (float)NVOX * 16.f;
    float mu = S / cnt; float var = Q / cnt - mu*mu;
    float rs = rsqrtf(var + GEPS);
    float y = (d_grid1[i] - mu) * rs * g[c] + bt[c];
    d_grid1[i] = y / (1.f + expf(-y));
}

// ---------------- GN2 per-channel stats (for GN + SE fold) -------------------
__global__ void k_cstats2() {
    int b = blockIdx.x >> 6, ch = blockIdx.x & 63;
    int c = threadIdx.x & 127, l2 = threadIdx.x >> 7;
    long base = ((long)b*NVOX + ch*512) * COUT;
    float s = 0.f, q = 0.f;
    for (int v = l2; v < 512; v += 2) {
        float x = d_grid2[base + (long)v*COUT + c];
        s += x; q += x*x;
    }
    __shared__ float ss[256], sq[256];
    ss[threadIdx.x] = s; sq[threadIdx.x] = q;
    __syncthreads();
    if (threadIdx.x < 128) {
        atomicAdd(&d_cstats2[(b*COUT + c)*2 + 0], ss[c] + ss[c+128]);
        atomicAdd(&d_cstats2[(b*COUT + c)*2 + 1], sq[c] + sq[c+128]);
    }
}

// ---------------- SE + fold GN2*SE into per-(b,c) affine ---------------------
__global__ void k_se(const float* __restrict__ w1, const float* __restrict__ b1,
                     const float* __restrict__ w2, const float* __restrict__ b2,
                     const float* __restrict__ gamma, const float* __restrict__ beta) {
    int b = blockIdx.x; int c = threadIdx.x;
    __shared__ float s[128], gmu[8], grs[8], s1[16];
    const float cnt = (float)NVOX;
    if (c < 8) {
        float S = 0.f, Q = 0.f;
        for (int j = 0; j < 16; j++) {
            S += d_cstats2[(b*COUT + c*16 + j)*2 + 0];
            Q += d_cstats2[(b*COUT + c*16 + j)*2 + 1];
        }
        float gc = cnt * 16.f;
        float mu = S / gc; float var = Q / gc - mu*mu;
        gmu[c] = mu; grs[c] = rsqrtf(var + GEPS);
    }
    __syncthreads();
    int gr = c >> 4;
    float mu = gmu[gr], rs = grs[gr];
    float csum = d_cstats2[(b*COUT + c)*2];
    s[c] = (csum / cnt - mu) * rs * gamma[c] + beta[c];
    __syncthreads();
    if (c < 16) {
        float a = b1[c];
        for (int j = 0; j < 128; j++) a += w1[c*128 + j] * s[j];
        s1[c] = fmaxf(a, 0.f);
    }
    __syncthreads();
    float a2 = b2[c];
    for (int j = 0; j < 16; j++) a2 += w2[c*16 + j] * s1[j];
    float se = 1.f / (1.f + expf(-a2));
    float rg = rs * gamma[c];
    d_A [b*COUT + c] = rg * se;
    d_Bc[b*COUT + c] = (beta[c] - mu * rg) * se;
}

// ---------------- point branch 1x1 conv + stats ------------------------------
__global__ void k_pt(const float* __restrict__ feat, const float* __restrict__ ptb) {
    int blk = blockIdx.x;
    int b = blk >> 10, n0 = (blk & 1023) * 32;
    __shared__ float fs[CIN*32];       // [ci][nn]
    __shared__ float so[32*COUT];      // [nn][o]
    __shared__ float ss[256], sq[256];
    for (int e = threadIdx.x; e < CIN*32; e += 256) {
        int ci = e >> 5, nn = e & 31;
        fs[e] = feat[((long)(b*CIN) + ci)*NPTS + n0 + nn];
    }
    __syncthreads();
    int o = threadIdx.x & 127, h = threadIdx.x >> 7;
    float acc[16];
    float bv = ptb[o];
    #pragma unroll
    for (int j = 0; j < 16; j++) acc[j] = bv;
    for (int ci = 0; ci < CIN; ci++) {
        float w = d_ptw[ci*COUT + o];
        #pragma unroll
        for (int j = 0; j < 16; j++)
            acc[j] = fmaf(w, fs[ci*32 + h*16 + j], acc[j]);
    }
    float s = 0.f, q = 0.f;
    #pragma unroll
    for (int j = 0; j < 16; j++) {
        s += acc[j]; q += acc[j]*acc[j];
        so[(h*16 + j)*COUT + o] = acc[j];
    }
    ss[threadIdx.x] = s; sq[threadIdx.x] = q;
    __syncthreads();
    if (threadIdx.x < 8) {
        float S = 0.f, Q = 0.f;
        for (int j = 0; j < 16; j++) {
            int cc = threadIdx.x*16 + j;
            S += ss[cc] + ss[cc+128]; Q += sq[cc] + sq[cc+128];
        }
        atomicAdd(&d_ptstats[(b*8 + threadIdx.x)*2 + 0], S);
        atomicAdd(&d_ptstats[(b*8 + threadIdx.x)*2 + 1], Q);
    }
    for (int e = threadIdx.x; e < 32*COUT; e += 256) {
        int nn = e >> 7, oo = e & 127;
        d_pt[((long)(b*NPTS) + n0 + nn)*COUT + oo] = so[e];
    }
}

__global__ void k_ptab(const float* __restrict__ g, const float* __restrict__ bt) {
    int i = blockIdx.x * 256 + threadIdx.x;
    if (i >= BB*COUT) return;
    int b = i >> 7, c = i & 127, gr = c >> 4;
    const float cnt = 16.f * (float)NPTS;
    float S = d_ptstats[(b*8 + gr)*2], Q = d_ptstats[(b*8 + gr)*2 + 1];
    float mu = S / cnt, var = Q / cnt - mu*mu, rs = rsqrtf(var + GEPS);
    d_ptA[i] = rs * g[c];
    d_ptB[i] = bt[c] - mu * rs * g[c];
}

// ---------------- trilinear devoxelize + point add -> out (coalesced) --------
__global__ void k_out(float* __restrict__ out) {
    __shared__ float so[64*132];
    int warp = threadIdx.x >> 5, lane = threadIdx.x & 31;
    int blk = blockIdx.x;                 // BB*NPTS/64 blocks
    int b = blk >> 9;
    int n0 = (blk & 511) * 64;

    #pragma unroll 1
    for (int pass = 0; pass < 8; pass++) {
        int pt = pass * 8 + warp;
        int n = n0 + pt;
        float nx = d_normc[(b*3+0)*NPTS + n];
        float ny = d_normc[(b*3+1)*NPTS + n];
        float nz = d_normc[(b*3+2)*NPTS + n];
        int lx = (int)floorf(nx); float fx = nx - (float)lx; int hx = min(lx+1, RES-1);
        int ly = (int)floorf(ny); float fy = ny - (float)ly; int hy = min(ly+1, RES-1);
        int lz = (int)floorf(nz); float fz = nz - (float)lz; int hz = min(lz+1, RES-1);

        float4 acc = make_float4(0.f, 0.f, 0.f, 0.f);
        float sumw = 0.f;
        const float4* gp = (const float4*)d_grid2;
        #pragma unroll
        for (int k = 0; k < 8; k++) {
            int dx = k >> 2, dy = (k >> 1) & 1, dz = k & 1;
            int ix = dx ? hx : lx, iy = dy ? hy : ly, iz = dz ? hz : lz;
            float w = (dx ? fx : 1.f - fx) * (dy ? fy : 1.f - fy) * (dz ? fz : 1.f - fz);
            long row = ((long)(b*NVOX) + (ix*RES + iy)*RES + iz) * (COUT/4);
            float4 v = gp[row + lane];
            acc.x += w*v.x; acc.y += w*v.y; acc.z += w*v.z; acc.w += w*v.w;
            sumw += w;
        }
        float4 a  = ((const float4*)d_A )[b*32 + lane];
        float4 bc = ((const float4*)d_Bc)[b*32 + lane];
        float4 gv;
        gv.x = acc.x*a.x + sumw*bc.x; gv.y = acc.y*a.y + sumw*bc.y;
        gv.z = acc.z*a.z + sumw*bc.z; gv.w = acc.w*a.w + sumw*bc.w;

        float4 pv = ((const float4*)d_pt)[((long)(b*NPTS) + n)*32 + lane];
        float4 pa = ((const float4*)d_ptA)[b*32 + lane];
        float4 pb = ((const float4*)d_ptB)[b*32 + lane];
        float y;
        y = pv.x*pa.x + pb.x; gv.x += y / (1.f + expf(-y));
        y = pv.y*pa.y + pb.y; gv.y += y / (1.f + expf(-y));
        y = pv.z*pa.z + pb.z; gv.z += y / (1.f + expf(-y));
        y = pv.w*pa.w + pb.w; gv.w += y / (1.f + expf(-y));

        ((float4*)(so + pt*132))[lane] = gv;
    }
    __syncthreads();
    for (int e = threadIdx.x; e < 64*128; e += 256) {
        int c = e >> 6, n = e & 63;
        out[((long)(b*COUT) + c)*NPTS + n0 + n] = so[n*132 + c];
    }
}

// ---------------- launch ------------------------------------------------------
extern "C" void kernel_launch(void* const* d_in, const int* in_sizes, int n_in,
                              void* d_out, int out_size) {
    const float* features = (const float*)d_in[0];
    const float* coords   = (const float*)d_in[1];
    const float* conv1_w  = (const float*)d_in[2];
    const float* conv1_b  = (const float*)d_in[3];
    const float* gn1_g    = (const float*)d_in[4];
    const float* gn1_b    = (const float*)d_in[5];
    const float* conv2_w  = (const float*)d_in[6];
    const float* conv2_b  = (const float*)d_in[7];
    const float* gn2_g    = (const float*)d_in[8];
    const float* gn2_b    = (const float*)d_in[9];
    const float* se_w1    = (const float*)d_in[10];
    const float* se_b1    = (const float*)d_in[11];
    const float* se_w2    = (const float*)d_in[12];
    const float* se_b2    = (const float*)d_in[13];
    const float* pt_w     = (const float*)d_in[14];
    const float* pt_b     = (const float*)d_in[15];
    const float* ptgn_g   = (const float*)d_in[16];
    const float* ptgn_b   = (const float*)d_in[17];
    float* out = (float*)d_out;

    k_prep<<<(COUT*27*COUT + 255)/256, 256>>>(conv1_w, conv2_w, pt_w);
    k_zero<<<(BB*NVOX*CIN)/256, 256>>>();
    k_mean1<<<BB*3*16, 256>>>(coords);
    k_scale1<<<BB*16, 256>>>(coords);
    k_norm<<<(BB*3*NPTS + 255)/256, 256>>>(coords);
    k_scatter<<<BB*NPTS/8, 256>>>(features);
    k_div<<<(BB*NVOX*CIN)/256, 256>>>();
    k_conv<CIN,0><<<BB*RES*RES, 256>>>(conv1_b);
    k_gstats1<<<BB*64, 256>>>();
    k_gn1<<<(BB*NVOX*COUT)/256, 256>>>(gn1_g, gn1_b);
    k_conv<COUT,1><<<BB*RES*RES, 256>>>(conv2_b);
    k_cstats2<<<BB*64, 256>>>();
    k_se<<<BB, 128>>>(se_w1, se_b1, se_w2, se_b2, gn2_g, gn2_b);
    k_pt<<<BB*(NPTS/32), 256>>>(features, pt_b);
    k_ptab<<<(BB*COUT + 255)/256, 256>>>(ptgn_g, ptgn_b);
    k_out<<<BB*NPTS/64, 256>>>(out);
}

// round 6
// speedup vs baseline: 4.7926x; 2.6349x over previous
#include <cuda_runtime.h>
#include <math.h>
#include <stdint.h>

#define BB 8
#define CIN 64
#define COUT 128
#define NPTS 32768
#define RES 32
#define NVOX (RES*RES*RES)
#define GEPS 1e-5f

#define PX 34
#define PY 36
#define PZ 34
#define PVOX (PX*PY*PZ)          // 41616
#define SLK 2048                 // halo slack rows each side
#define NTILE 326                // ceil(PVOX/128)

// ---------------- scratch (static device globals; no allocation) -------------
__device__ float d_msum[BB*3];
__device__ unsigned d_smaxu[BB];
__device__ float d_normc[BB*3*NPTS];
__device__ __align__(16) float d_gp0[((long)BB*PVOX + 2*SLK)*CIN];   //  86 MB padded tf32 in (conv1)
__device__ __align__(16) float d_gp1[((long)BB*PVOX + 2*SLK)*COUT];  // 173 MB padded tf32 in (conv2)
__device__ float d_cnt[BB*NVOX];
__device__ float d_grid1[(long)BB*NVOX*COUT];   // compact conv1 out
__device__ float d_grid2[(long)BB*NVOX*COUT];   // compact conv2 out
__device__ float d_pt[(long)BB*NPTS*COUT];      // point branch
__device__ __align__(16) float d_wb1[27*COUT*CIN];   // [t][o][ci] tf32
__device__ __align__(16) float d_wb2[27*COUT*COUT];
__device__ float d_ptw[CIN*COUT];
__device__ float d_gstats1[BB*8*2];
__device__ float d_cstats2[BB*COUT*2];
__device__ float d_ptstats[BB*8*2];
__device__ float d_A[BB*COUT];
__device__ float d_Bc[BB*COUT];
__device__ float d_ptA[BB*COUT];
__device__ float d_ptB[BB*COUT];

// ---------------- helpers -----------------------------------------------------
__device__ __forceinline__ float rtf32(float x) {
    float r; asm("cvt.rna.tf32.f32 %0, %1;" : "=f"(r) : "f"(x)); return r;
}
__device__ __forceinline__ uint32_t smem_u32(const void* p) {
    uint32_t a;
    asm("{ .reg .u64 t; cvta.to.shared.u64 t, %1; cvt.u32.u64 %0, t; }" : "=r"(a) : "l"(p));
    return a;
}
__device__ __forceinline__ void cpa16(uint32_t dst, const void* src) {
    asm volatile("cp.async.cg.shared.global [%0], [%1], 16;" :: "r"(dst), "l"(src));
}
__device__ __forceinline__ void mma_tf32(float& d0, float& d1, float& d2, float& d3,
                                         uint32_t a0, uint32_t a1, uint32_t a2, uint32_t a3,
                                         uint32_t b0, uint32_t b1) {
    asm volatile(
        "mma.sync.aligned.m16n8k8.row.col.f32.tf32.tf32.f32 "
        "{%0,%1,%2,%3}, {%4,%5,%6,%7}, {%8,%9}, {%0,%1,%2,%3};"
        : "+f"(d0), "+f"(d1), "+f"(d2), "+f"(d3)
        : "r"(a0), "r"(a1), "r"(a2), "r"(a3), "r"(b0), "r"(b1));
}

// ---------------- prep: weights -> [t][o][ci] tf32 ---------------------------
__global__ void k_prep(const float* __restrict__ w1, const float* __restrict__ w2,
                       const float* __restrict__ ptw) {
    int i = blockIdx.x * 256 + threadIdx.x;          // grid covers 27*128*128
    if (i < 27*COUT*CIN) {                           // wb1[(t*128+o)*64+ci]
        int ci = i % CIN; int r = i / CIN; int o = r & 127; int t = r >> 7;
        d_wb1[i] = rtf32(w1[(o*CIN + ci)*27 + t]);
    }
    if (i < 27*COUT*COUT) {
        int ci = i & 127; int r = i >> 7; int o = r & 127; int t = r >> 7;
        d_wb2[i] = rtf32(w2[(o*COUT + ci)*27 + t]);
    }
    if (i < CIN*COUT) {
        int o = i & 127; int ci = i >> 7;
        d_ptw[i] = ptw[o*CIN + ci];
    }
}

__global__ void k_zero() {
    long i = (long)blockIdx.x * 256 + threadIdx.x;   // ((BB*PVOX+2*SLK)*COUT)/256 blocks
    d_gp1[i] = 0.f;
    if (i < ((long)BB*PVOX + 2*SLK)*CIN) d_gp0[i] = 0.f;
    if (i < BB*NVOX)   d_cnt[i] = 0.f;
    if (i < BB*8*2)    d_gstats1[i] = 0.f;
    if (i < BB*COUT*2) d_cstats2[i] = 0.f;
    if (i < BB*8*2)    d_ptstats[i] = 0.f;
    if (i < BB*3)      d_msum[i] = 0.f;
    if (i < BB)        d_smaxu[i] = 0u;
}

// ---------------- voxelize coords ---------------------------------------------
__global__ void k_mean1(const float* __restrict__ coords) {
    int blk = blockIdx.x;
    int chunk = blk & 15; int d = (blk >> 4) % 3; int b = blk / 48;
    __shared__ float s[256];
    float acc = 0.f;
    int base = (b*3 + d)*NPTS + chunk*2048;
    for (int n = threadIdx.x; n < 2048; n += 256) acc += coords[base + n];
    s[threadIdx.x] = acc; __syncthreads();
    for (int o = 128; o > 0; o >>= 1) {
        if (threadIdx.x < o) s[threadIdx.x] += s[threadIdx.x + o];
        __syncthreads();
    }
    if (threadIdx.x == 0) atomicAdd(&d_msum[b*3 + d], s[0]);
}

__global__ void k_scale1(const float* __restrict__ coords) {
    int blk = blockIdx.x;
    int chunk = blk & 15; int b = blk >> 4;
    float mx = d_msum[b*3]   * (1.f/(float)NPTS);
    float my = d_msum[b*3+1] * (1.f/(float)NPTS);
    float mz = d_msum[b*3+2] * (1.f/(float)NPTS);
    __shared__ float s[256];
    float m = 0.f;
    int n0 = chunk*2048;
    for (int n = threadIdx.x; n < 2048; n += 256) {
        float x = coords[(b*3+0)*NPTS + n0 + n] - mx;
        float y = coords[(b*3+1)*NPTS + n0 + n] - my;
        float z = coords[(b*3+2)*NPTS + n0 + n] - mz;
        m = fmaxf(m, sqrtf(x*x + y*y + z*z));
    }
    s[threadIdx.x] = m; __syncthreads();
    for (int o = 128; o > 0; o >>= 1) {
        if (threadIdx.x < o) s[threadIdx.x] = fmaxf(s[threadIdx.x], s[threadIdx.x + o]);
        __syncthreads();
    }
    if (threadIdx.x == 0) atomicMax(&d_smaxu[b], __float_as_uint(s[0]));
}

__global__ void k_norm(const float* __restrict__ coords) {
    int i = blockIdx.x * 256 + threadIdx.x;
    if (i >= BB*3*NPTS) return;
    int b = i / (3*NPTS); int d = (i / NPTS) % 3;
    float mean = d_msum[b*3 + d] * (1.f/(float)NPTS);
    float scale = __uint_as_float(d_smaxu[b]) * 2.f;
    float t = (coords[i] - mean) / scale + 0.5f;
    d_normc[i] = fminf(fmaxf(t * (float)RES, 0.f), (float)(RES - 1));
}

// ---------------- scatter-mean voxelization into padded grid -----------------
__global__ void k_scatter(const float* __restrict__ feat) {
    int warp = threadIdx.x >> 5, lane = threadIdx.x & 31;
    int p = blockIdx.x * 8 + warp;
    int b = p >> 15, n = p & (NPTS - 1);
    int ix = min(max((int)rintf(d_normc[(b*3+0)*NPTS + n]), 0), RES-1);
    int iy = min(max((int)rintf(d_normc[(b*3+1)*NPTS + n]), 0), RES-1);
    int iz = min(max((int)rintf(d_normc[(b*3+2)*NPTS + n]), 0), RES-1);
    int pp = ((ix+1)*PY + (iy+1))*PZ + (iz+1);
    const float* frow = feat + (long)b*CIN*NPTS + n;
    float v0 = frow[(long)lane * NPTS];
    float v1 = frow[(long)(lane + 32) * NPTS];
    float* row = d_gp0 + ((long)SLK + (long)b*PVOX + pp) * CIN;
    atomicAdd(&row[lane],      v0);
    atomicAdd(&row[lane + 32], v1);
    if (lane == 0) atomicAdd(&d_cnt[b*NVOX + ((ix*RES + iy)*RES + iz)], 1.f);
}

__global__ void k_div() {
    long i = (long)blockIdx.x * 256 + threadIdx.x;   // BB*NVOX*CIN
    int c = i & 63; int v = (int)((i >> 6) & (NVOX-1)); int b = (int)(i >> 21);
    int x = v >> 10, y = (v >> 5) & 31, z = v & 31;
    int pp = ((x+1)*PY + (y+1))*PZ + (z+1);
    float cntv = fmaxf(d_cnt[b*NVOX + v], 1.f);
    float* a = d_gp0 + ((long)SLK + (long)b*PVOX + pp) * CIN + c;
    *a = rtf32(*a / cntv);
}

// ---------------- tf32 mma.sync implicit-GEMM 3x3x3 conv ----------------------
// CTA: 256 thr = 8 warps (4 m x 2 n). Tile: M=128 padded voxels, N=128 outs.
// Per (tap, ci-chunk of 32): stage A[128][32] + B[128][32] (pad-36 rows) via
// cp.async, then 4 K=8 steps of mma.m16n8k8 tf32. Warp computes 32x64.
template<int CI, int STAGE>
__global__ void __launch_bounds__(256) k_tconv(const float* __restrict__ bias) {
    __shared__ __align__(16) float sA[128*36];
    __shared__ __align__(16) float sB[128*36];

    const float* __restrict__ gin = (STAGE == 0) ? (d_gp0 + (long)SLK*CI)
                                                 : (d_gp1 + (long)SLK*CI);
    const float* __restrict__ wb  = (STAGE == 0) ? d_wb1 : d_wb2;
    float*       __restrict__ gout = (STAGE == 0) ? d_grid1 : d_grid2;

    int blk = blockIdx.x;                   // BB*NTILE
    int b = blk / NTILE, tile = blk % NTILE;
    long pbase = (long)b * PVOX + tile * 128;

    int tid = threadIdx.x, warp = tid >> 5, lane = tid & 31;
    int wm = warp & 3, wn = warp >> 2;      // warp tile rows wm*32, cols wn*64
    uint32_t aA = smem_u32(sA), aB = smem_u32(sB);

    float acc[2][8][4];
    #pragma unroll
    for (int mi = 0; mi < 2; mi++)
        #pragma unroll
        for (int ni = 0; ni < 8; ni++)
            #pragma unroll
            for (int j = 0; j < 4; j++) acc[mi][ni][j] = 0.f;

    // per-lane fragment smem offsets (floats)
    int q = lane >> 2, rr = lane & 3;
    const uint32_t* sAu = (const uint32_t*)sA;
    const uint32_t* sBu = (const uint32_t*)sB;
    int aoffs = (wm*32 + q)*36 + rr;        // + mi*16*36 + ks*8 (+4 for hi k)
    int boffs = (wn*64 + q)*36 + rr;        // + ni*8*36  + ks*8 (+4)

    const int NCK = CI / 32;
    #pragma unroll 1
    for (int t = 0; t < 27; t++) {
        int dxx = t / 9 - 1, dyy = (t / 3) % 3 - 1, dzz = t % 3 - 1;
        long aoff = pbase + dxx * (PY*PZ) + dyy * PZ + dzz;
        #pragma unroll 1
        for (int ck = 0; ck < NCK; ck++) {
            __syncthreads();                // smem safe to overwrite
            const float* asrc = gin + aoff * CI + ck * 32;
            #pragma unroll
            for (int o2 = 0; o2 < 4; o2++) {
                int i = o2 * 256 + tid; int r = i >> 3, seg = i & 7;
                cpa16(aA + (uint32_t)(r*144 + seg*16), asrc + (long)r * CI + seg*4);
            }
            const float* bsrc = wb + (long)(t * COUT) * CI + ck * 32;
            #pragma unroll
            for (int o2 = 0; o2 < 4; o2++) {
                int i = o2 * 256 + tid; int r = i >> 3, seg = i & 7;
                cpa16(aB + (uint32_t)(r*144 + seg*16), bsrc + (long)r * CI + seg*4);
            }
            asm volatile("cp.async.commit_group;");
            asm volatile("cp.async.wait_group 0;");
            __syncthreads();

            #pragma unroll
            for (int ks = 0; ks < 4; ks++) {
                int k0 = ks * 8;
                uint32_t a0[2], a1[2], a2[2], a3[2];
                #pragma unroll
                for (int mi = 0; mi < 2; mi++) {
                    int base = aoffs + mi*16*36 + k0;
                    a0[mi] = sAu[base];
                    a1[mi] = sAu[base + 8*36];
                    a2[mi] = sAu[base + 4];
                    a3[mi] = sAu[base + 8*36 + 4];
                }
                #pragma unroll
                for (int ni = 0; ni < 8; ni++) {
                    int base = boffs + ni*8*36 + k0;
                    uint32_t b0 = sBu[base];
                    uint32_t b1 = sBu[base + 4];
                    mma_tf32(acc[0][ni][0], acc[0][ni][1], acc[0][ni][2], acc[0][ni][3],
                             a0[0], a1[0], a2[0], a3[0], b0, b1);
                    mma_tf32(acc[1][ni][0], acc[1][ni][1], acc[1][ni][2], acc[1][ni][3],
                             a0[1], a1[1], a2[1], a3[1], b0, b1);
                }
            }
        }
    }

    // epilogue: discard pad rows, add bias, store compact channels-last
    int cb = wn*64 + (lane & 3)*2;
    int prow = tile*128 + wm*32 + (lane >> 2);
    #pragma unroll
    for (int mi = 0; mi < 2; mi++) {
        int p0 = prow + mi*16;
        #pragma unroll
        for (int half = 0; half < 2; half++) {
            int pp = p0 + half*8;
            int zp = pp % PZ; int rem = pp / PZ; int yp = rem % PY; int xp = rem / PY;
            bool valid = (pp < PVOX) && (xp >= 1 && xp <= 32) && (yp >= 1 && yp <= 32)
                         && (zp >= 1 && zp <= 32);
            if (!valid) continue;
            long ob = ((long)b*NVOX + (((xp-1)*RES + (yp-1))*RES + (zp-1))) * COUT;
            #pragma unroll
            for (int ni = 0; ni < 8; ni++) {
                int col = cb + ni*8;
                float2 o2;
                o2.x = acc[mi][ni][half*2]   + bias[col];
                o2.y = acc[mi][ni][half*2+1] + bias[col+1];
                *(float2*)&gout[ob + col] = o2;
            }
        }
    }
}

// ---------------- GN1 stats + normalize+swish -> padded tf32 gp1 -------------
__global__ void k_gstats1() {
    int b = blockIdx.x >> 6, ch = blockIdx.x & 63;
    int c = threadIdx.x & 127, l2 = threadIdx.x >> 7;
    long base = ((long)b*NVOX + ch*512) * COUT;
    float s = 0.f, q = 0.f;
    for (int v = l2; v < 512; v += 2) {
        float x = d_grid1[base + (long)v*COUT + c];
        s += x; q += x*x;
    }
    __shared__ float ss[256], sq[256];
    ss[threadIdx.x] = s; sq[threadIdx.x] = q;
    __syncthreads();
    if (threadIdx.x < 8) {
        float S = 0.f, Q = 0.f;
        for (int j = 0; j < 16; j++) {
            int cc = threadIdx.x*16 + j;
            S += ss[cc] + ss[cc+128]; Q += sq[cc] + sq[cc+128];
        }
        atomicAdd(&d_gstats1[(b*8 + threadIdx.x)*2 + 0], S);
        atomicAdd(&d_gstats1[(b*8 + threadIdx.x)*2 + 1], Q);
    }
}

__global__ void k_gn1(const float* __restrict__ g, const float* __restrict__ bt) {
    long i = (long)blockIdx.x * 256 + threadIdx.x;   // BB*NVOX*COUT
    int c = i & 127; int b = (int)(i >> 22);
    int v = (int)((i >> 7) & (NVOX-1));
    int gr = c >> 4;
    float S = d_gstats1[(b*8 + gr)*2], Q = d_gstats1[(b*8 + gr)*2 + 1];
    const float cnt = (float)NVOX * 16.f;
    float mu = S / cnt; float var = Q / cnt - mu*mu;
    float rs = rsqrtf(var + GEPS);
    float y = (d_grid1[i] - mu) * rs * g[c] + bt[c];
    float sw = y / (1.f + expf(-y));
    int x = v >> 10, yy = (v >> 5) & 31, z = v & 31;
    int pp = ((x+1)*PY + (yy+1))*PZ + (z+1);
    d_gp1[((long)SLK + (long)b*PVOX + pp)*COUT + c] = rtf32(sw);
}

// ---------------- GN2 per-channel stats ---------------------------------------
__global__ void k_cstats2() {
    int b = blockIdx.x >> 6, ch = blockIdx.x & 63;
    int c = threadIdx.x & 127, l2 = threadIdx.x >> 7;
    long base = ((long)b*NVOX + ch*512) * COUT;
    float s = 0.f, q = 0.f;
    for (int v = l2; v < 512; v += 2) {
        float x = d_grid2[base + (long)v*COUT + c];
        s += x; q += x*x;
    }
    __shared__ float ss[256], sq[256];
    ss[threadIdx.x] = s; sq[threadIdx.x] = q;
    __syncthreads();
    if (threadIdx.x < 128) {
        atomicAdd(&d_cstats2[(b*COUT + c)*2 + 0], ss[c] + ss[c+128]);
        atomicAdd(&d_cstats2[(b*COUT + c)*2 + 1], sq[c] + sq[c+128]);
    }
}

// ---------------- SE + fold GN2*SE into per-(b,c) affine ---------------------
__global__ void k_se(const float* __restrict__ w1, const float* __restrict__ b1,
                     const float* __restrict__ w2, const float* __restrict__ b2,
                     const float* __restrict__ gamma, const float* __restrict__ beta) {
    int b = blockIdx.x; int c = threadIdx.x;
    __shared__ float s[128], gmu[8], grs[8], s1[16];
    const float cnt = (float)NVOX;
    if (c < 8) {
        float S = 0.f, Q = 0.f;
        for (int j = 0; j < 16; j++) {
            S += d_cstats2[(b*COUT + c*16 + j)*2 + 0];
            Q += d_cstats2[(b*COUT + c*16 + j)*2 + 1];
        }
        float gc = cnt * 16.f;
        float mu = S / gc; float var = Q / gc - mu*mu;
        gmu[c] = mu; grs[c] = rsqrtf(var + GEPS);
    }
    __syncthreads();
    int gr = c >> 4;
    float mu = gmu[gr], rs = grs[gr];
    float csum = d_cstats2[(b*COUT + c)*2];
    s[c] = (csum / cnt - mu) * rs * gamma[c] + beta[c];
    __syncthreads();
    if (c < 16) {
        float a = b1[c];
        for (int j = 0; j < 128; j++) a += w1[c*128 + j] * s[j];
        s1[c] = fmaxf(a, 0.f);
    }
    __syncthreads();
    float a2 = b2[c];
    for (int j = 0; j < 16; j++) a2 += w2[c*16 + j] * s1[j];
    float se = 1.f / (1.f + expf(-a2));
    float rg = rs * gamma[c];
    d_A [b*COUT + c] = rg * se;
    d_Bc[b*COUT + c] = (beta[c] - mu * rg) * se;
}

// ---------------- point branch 1x1 conv + stats --------------------------------
__global__ void k_pt(const float* __restrict__ feat, const float* __restrict__ ptb) {
    int blk = blockIdx.x;
    int b = blk >> 10, n0 = (blk & 1023) * 32;
    __shared__ float fs[CIN*32];
    __shared__ float so[32*COUT];
    __shared__ float ss[256], sq[256];
    for (int e = threadIdx.x; e < CIN*32; e += 256) {
        int ci = e >> 5, nn = e & 31;
        fs[e] = feat[((long)(b*CIN) + ci)*NPTS + n0 + nn];
    }
    __syncthreads();
    int o = threadIdx.x & 127, h = threadIdx.x >> 7;
    float acc[16];
    float bv = ptb[o];
    #pragma unroll
    for (int j = 0; j < 16; j++) acc[j] = bv;
    for (int ci = 0; ci < CIN; ci++) {
        float w = d_ptw[ci*COUT + o];
        #pragma unroll
        for (int j = 0; j < 16; j++)
            acc[j] = fmaf(w, fs[ci*32 + h*16 + j], acc[j]);
    }
    float s = 0.f, q = 0.f;
    #pragma unroll
    for (int j = 0; j < 16; j++) {
        s += acc[j]; q += acc[j]*acc[j];
        so[(h*16 + j)*COUT + o] = acc[j];
    }
    ss[threadIdx.x] = s; sq[threadIdx.x] = q;
    __syncthreads();
    if (threadIdx.x < 8) {
        float S = 0.f, Q = 0.f;
        for (int j = 0; j < 16; j++) {
            int cc = threadIdx.x*16 + j;
            S += ss[cc] + ss[cc+128]; Q += sq[cc] + sq[cc+128];
        }
        atomicAdd(&d_ptstats[(b*8 + threadIdx.x)*2 + 0], S);
        atomicAdd(&d_ptstats[(b*8 + threadIdx.x)*2 + 1], Q);
    }
    for (int e = threadIdx.x; e < 32*COUT; e += 256) {
        int nn = e >> 7, oo = e & 127;
        d_pt[((long)(b*NPTS) + n0 + nn)*COUT + oo] = so[e];
    }
}

__global__ void k_ptab(const float* __restrict__ g, const float* __restrict__ bt) {
    int i = blockIdx.x * 256 + threadIdx.x;
    if (i >= BB*COUT) return;
    int b = i >> 7, c = i & 127, gr = c >> 4;
    const float cnt = 16.f * (float)NPTS;
    float S = d_ptstats[(b*8 + gr)*2], Q = d_ptstats[(b*8 + gr)*2 + 1];
    float mu = S / cnt, var = Q / cnt - mu*mu, rs = rsqrtf(var + GEPS);
    d_ptA[i] = rs * g[c];
    d_ptB[i] = bt[c] - mu * rs * g[c];
}

// ---------------- trilinear devoxelize + point add -> out (coalesced) ---------
__global__ void k_out(float* __restrict__ out) {
    __shared__ float so[64*132];
    int warp = threadIdx.x >> 5, lane = threadIdx.x & 31;
    int blk = blockIdx.x;
    int b = blk >> 9;
    int n0 = (blk & 511) * 64;

    #pragma unroll 1
    for (int pass = 0; pass < 8; pass++) {
        int pt = pass * 8 + warp;
        int n = n0 + pt;
        float nx = d_normc[(b*3+0)*NPTS + n];
        float ny = d_normc[(b*3+1)*NPTS + n];
        float nz = d_normc[(b*3+2)*NPTS + n];
        int lx = (int)floorf(nx); float fx = nx - (float)lx; int hx = min(lx+1, RES-1);
        int ly = (int)floorf(ny); float fy = ny - (float)ly; int hy = min(ly+1, RES-1);
        int lz = (int)floorf(nz); float fz = nz - (float)lz; int hz = min(lz+1, RES-1);

        float4 acc = make_float4(0.f, 0.f, 0.f, 0.f);
        float sumw = 0.f;
        const float4* gp = (const float4*)d_grid2;
        #pragma unroll
        for (int k = 0; k < 8; k++) {
            int dx = k >> 2, dy = (k >> 1) & 1, dz = k & 1;
            int ix = dx ? hx : lx, iy = dy ? hy : ly, iz = dz ? hz : lz;
            float w = (dx ? fx : 1.f - fx) * (dy ? fy : 1.f - fy) * (dz ? fz : 1.f - fz);
            long row = ((long)(b*NVOX) + (ix*RES + iy)*RES + iz) * (COUT/4);
            float4 v = gp[row + lane];
            acc.x += w*v.x; acc.y += w*v.y; acc.z += w*v.z; acc.w += w*v.w;
            sumw += w;
        }
        float4 a  = ((const float4*)d_A )[b*32 + lane];
        float4 bc = ((const float4*)d_Bc)[b*32 + lane];
        float4 gv;
        gv.x = acc.x*a.x + sumw*bc.x; gv.y = acc.y*a.y + sumw*bc.y;
        gv.z = acc.z*a.z + sumw*bc.z; gv.w = acc.w*a.w + sumw*bc.w;

        float4 pv = ((const float4*)d_pt)[((long)(b*NPTS) + n)*32 + lane];
        float4 pa = ((const float4*)d_ptA)[b*32 + lane];
        float4 pb = ((const float4*)d_ptB)[b*32 + lane];
        float y;
        y = pv.x*pa.x + pb.x; gv.x += y / (1.f + expf(-y));
        y = pv.y*pa.y + pb.y; gv.y += y / (1.f + expf(-y));
        y = pv.z*pa.z + pb.z; gv.z += y / (1.f + expf(-y));
        y = pv.w*pa.w + pb.w; gv.w += y / (1.f + expf(-y));

        ((float4*)(so + pt*132))[lane] = gv;
    }
    __syncthreads();
    for (int e = threadIdx.x; e < 64*128; e += 256) {
        int c = e >> 6, n = e & 63;
        out[((long)(b*COUT) + c)*NPTS + n0 + n] = so[n*132 + c];
    }
}

// ---------------- launch --------------------------------------------------------
extern "C" void kernel_launch(void* const* d_in, const int* in_sizes, int n_in,
                              void* d_out, int out_size) {
    const float* features = (const float*)d_in[0];
    const float* coords   = (const float*)d_in[1];
    const float* conv1_w  = (const float*)d_in[2];
    const float* conv1_b  = (const float*)d_in[3];
    const float* gn1_g    = (const float*)d_in[4];
    const float* gn1_b    = (const float*)d_in[5];
    const float* conv2_w  = (const float*)d_in[6];
    const float* conv2_b  = (const float*)d_in[7];
    const float* gn2_g    = (const float*)d_in[8];
    const float* gn2_b    = (const float*)d_in[9];
    const float* se_w1    = (const float*)d_in[10];
    const float* se_b1    = (const float*)d_in[11];
    const float* se_w2    = (const float*)d_in[12];
    const float* se_b2    = (const float*)d_in[13];
    const float* pt_w     = (const float*)d_in[14];
    const float* pt_b     = (const float*)d_in[15];
    const float* ptgn_g   = (const float*)d_in[16];
    const float* ptgn_b   = (const float*)d_in[17];
    float* out = (float*)d_out;

    const long GP1SZ = ((long)BB*PVOX + 2*SLK) * COUT;

    k_prep<<<(27*COUT*COUT + 255)/256, 256>>>(conv1_w, conv2_w, pt_w);
    k_zero<<<(int)(GP1SZ/256), 256>>>();
    k_mean1<<<BB*3*16, 256>>>(coords);
    k_scale1<<<BB*16, 256>>>(coords);
    k_norm<<<(BB*3*NPTS + 255)/256, 256>>>(coords);
    k_scatter<<<BB*NPTS/8, 256>>>(features);
    k_div<<<(BB*NVOX*CIN)/256, 256>>>();
    k_tconv<CIN,0><<<BB*NTILE, 256>>>(conv1_b);
    k_gstats1<<<BB*64, 256>>>();
    k_gn1<<<(BB*NVOX*COUT)/256, 256>>>(gn1_g, gn1_b);
    k_tconv<COUT,1><<<BB*NTILE, 256>>>(conv2_b);
    k_cstats2<<<BB*64, 256>>>();
    k_se<<<BB, 128>>>(se_w1, se_b1, se_w2, se_b2, gn2_g, gn2_b);
    k_pt<<<BB*(NPTS/32), 256>>>(features, pt_b);
    k_ptab<<<(BB*COUT + 255)/256, 256>>>(ptgn_g, ptgn_b);
    k_out<<<BB*NPTS/64, 256>>>(out);
}

// round 8
// speedup vs baseline: 5.4654x; 1.1404x over previous
#include <cuda_runtime.h>
#include <math.h>
#include <stdint.h>

#define BB 8
#define CIN 64
#define COUT 128
#define NPTS 32768
#define RES 32
#define NVOX (RES*RES*RES)
#define GEPS 1e-5f

#define PX 34
#define PY 36
#define PZ 34
#define PVOX (PX*PY*PZ)          // 41616
#define SLK 2048                 // halo slack rows each side
#define NTILE 326                // ceil(PVOX/128)

// ---------------- scratch (static device globals; no allocation) -------------
__device__ float d_msum[BB*3];
__device__ unsigned d_smaxu[BB];
__device__ float d_normc[BB*3*NPTS];
__device__ __align__(16) float d_gp0[((long)BB*PVOX + 2*SLK)*CIN];   // padded tf32 in (conv1)
__device__ __align__(16) float d_gp1[((long)BB*PVOX + 2*SLK)*COUT];  // padded tf32 in (conv2)
__device__ float d_cnt[BB*NVOX];
__device__ float d_grid1[(long)BB*NVOX*COUT];   // compact conv1 out
__device__ float d_grid2[(long)BB*NVOX*COUT];   // compact conv2 out
__device__ float d_pt[(long)BB*NPTS*COUT];      // point branch
__device__ __align__(16) float d_wb1[27*COUT*CIN];   // [t][o][ci] tf32
__device__ __align__(16) float d_wb2[27*COUT*COUT];
__device__ float d_ptw[CIN*COUT];
__device__ float d_gstats1[BB*8*2];
__device__ float d_cstats2[BB*COUT*2];
__device__ float d_ptstats[BB*8*2];
__device__ float d_A[BB*COUT];
__device__ float d_Bc[BB*COUT];
__device__ float d_ptA[BB*COUT];
__device__ float d_ptB[BB*COUT];

// ---------------- helpers -----------------------------------------------------
__device__ __forceinline__ float rtf32(float x) {
    float r; asm("cvt.rna.tf32.f32 %0, %1;" : "=f"(r) : "f"(x)); return r;
}
__device__ __forceinline__ uint32_t smem_u32(const void* p) {
    uint32_t a;
    asm("{ .reg .u64 t; cvta.to.shared.u64 t, %1; cvt.u32.u64 %0, t; }" : "=r"(a) : "l"(p));
    return a;
}
__device__ __forceinline__ void cpa16(uint32_t dst, const void* src) {
    asm volatile("cp.async.cg.shared.global [%0], [%1], 16;" :: "r"(dst), "l"(src));
}
__device__ __forceinline__ void mma_tf32(float& d0, float& d1, float& d2, float& d3,
                                         uint32_t a0, uint32_t a1, uint32_t a2, uint32_t a3,
                                         uint32_t b0, uint32_t b1) {
    asm volatile(
        "mma.sync.aligned.m16n8k8.row.col.f32.tf32.tf32.f32 "
        "{%0,%1,%2,%3}, {%4,%5,%6,%7}, {%8,%9}, {%0,%1,%2,%3};"
        : "+f"(d0), "+f"(d1), "+f"(d2), "+f"(d3)
        : "r"(a0), "r"(a1), "r"(a2), "r"(a3), "r"(b0), "r"(b1));
}

// ---------------- prep: weights -> [t][o][ci] tf32 ---------------------------
__global__ void k_prep(const float* __restrict__ w1, const float* __restrict__ w2,
                       const float* __restrict__ ptw) {
    int i = blockIdx.x * 256 + threadIdx.x;
    if (i < 27*COUT*CIN) {
        int ci = i % CIN; int r = i / CIN; int o = r & 127; int t = r >> 7;
        d_wb1[i] = rtf32(w1[(o*CIN + ci)*27 + t]);
    }
    if (i < 27*COUT*COUT) {
        int ci = i & 127; int r = i >> 7; int o = r & 127; int t = r >> 7;
        d_wb2[i] = rtf32(w2[(o*COUT + ci)*27 + t]);
    }
    if (i < CIN*COUT) {
        int o = i & 127; int ci = i >> 7;
        d_ptw[i] = ptw[o*CIN + ci];
    }
}

__global__ void k_zero() {
    long i = (long)blockIdx.x * 256 + threadIdx.x;
    d_gp1[i] = 0.f;
    if (i < ((long)BB*PVOX + 2*SLK)*CIN) d_gp0[i] = 0.f;
    if (i < BB*NVOX)   d_cnt[i] = 0.f;
    if (i < BB*8*2)    d_gstats1[i] = 0.f;
    if (i < BB*COUT*2) d_cstats2[i] = 0.f;
    if (i < BB*8*2)    d_ptstats[i] = 0.f;
    if (i < BB*3)      d_msum[i] = 0.f;
    if (i < BB)        d_smaxu[i] = 0u;
}

// ---------------- voxelize coords ---------------------------------------------
__global__ void k_mean1(const float* __restrict__ coords) {
    int blk = blockIdx.x;
    int chunk = blk & 15; int d = (blk >> 4) % 3; int b = blk / 48;
    __shared__ float s[256];
    float acc = 0.f;
    int base = (b*3 + d)*NPTS + chunk*2048;
    for (int n = threadIdx.x; n < 2048; n += 256) acc += coords[base + n];
    s[threadIdx.x] = acc; __syncthreads();
    for (int o = 128; o > 0; o >>= 1) {
        if (threadIdx.x < o) s[threadIdx.x] += s[threadIdx.x + o];
        __syncthreads();
    }
    if (threadIdx.x == 0) atomicAdd(&d_msum[b*3 + d], s[0]);
}

__global__ void k_scale1(const float* __restrict__ coords) {
    int blk = blockIdx.x;
    int chunk = blk & 15; int b = blk >> 4;
    float mx = d_msum[b*3]   * (1.f/(float)NPTS);
    float my = d_msum[b*3+1] * (1.f/(float)NPTS);
    float mz = d_msum[b*3+2] * (1.f/(float)NPTS);
    __shared__ float s[256];
    float m = 0.f;
    int n0 = chunk*2048;
    for (int n = threadIdx.x; n < 2048; n += 256) {
        float x = coords[(b*3+0)*NPTS + n0 + n] - mx;
        float y = coords[(b*3+1)*NPTS + n0 + n] - my;
        float z = coords[(b*3+2)*NPTS + n0 + n] - mz;
        m = fmaxf(m, sqrtf(x*x + y*y + z*z));
    }
    s[threadIdx.x] = m; __syncthreads();
    for (int o = 128; o > 0; o >>= 1) {
        if (threadIdx.x < o) s[threadIdx.x] = fmaxf(s[threadIdx.x], s[threadIdx.x + o]);
        __syncthreads();
    }
    if (threadIdx.x == 0) atomicMax(&d_smaxu[b], __float_as_uint(s[0]));
}

__global__ void k_norm(const float* __restrict__ coords) {
    int i = blockIdx.x * 256 + threadIdx.x;
    if (i >= BB*3*NPTS) return;
    int b = i / (3*NPTS); int d = (i / NPTS) % 3;
    float mean = d_msum[b*3 + d] * (1.f/(float)NPTS);
    float scale = __uint_as_float(d_smaxu[b]) * 2.f;
    float t = (coords[i] - mean) / scale + 0.5f;
    d_normc[i] = fminf(fmaxf(t * (float)RES, 0.f), (float)(RES - 1));
}

// ---------------- scatter-mean voxelization into padded grid -----------------
__global__ void k_scatter(const float* __restrict__ feat) {
    int warp = threadIdx.x >> 5, lane = threadIdx.x & 31;
    int p = blockIdx.x * 8 + warp;
    int b = p >> 15, n = p & (NPTS - 1);
    int ix = min(max((int)rintf(d_normc[(b*3+0)*NPTS + n]), 0), RES-1);
    int iy = min(max((int)rintf(d_normc[(b*3+1)*NPTS + n]), 0), RES-1);
    int iz = min(max((int)rintf(d_normc[(b*3+2)*NPTS + n]), 0), RES-1);
    int pp = ((ix+1)*PY + (iy+1))*PZ + (iz+1);
    const float* frow = feat + (long)b*CIN*NPTS + n;
    float v0 = frow[(long)lane * NPTS];
    float v1 = frow[(long)(lane + 32) * NPTS];
    float* row = d_gp0 + ((long)SLK + (long)b*PVOX + pp) * CIN;
    atomicAdd(&row[lane],      v0);
    atomicAdd(&row[lane + 32], v1);
    if (lane == 0) atomicAdd(&d_cnt[b*NVOX + ((ix*RES + iy)*RES + iz)], 1.f);
}

__global__ void k_div() {
    long i = (long)blockIdx.x * 256 + threadIdx.x;
    int c = i & 63; int v = (int)((i >> 6) & (NVOX-1)); int b = (int)(i >> 21);
    int x = v >> 10, y = (v >> 5) & 31, z = v & 31;
    int pp = ((x+1)*PY + (y+1))*PZ + (z+1);
    float cntv = fmaxf(d_cnt[b*NVOX + v], 1.f);
    float* a = d_gp0 + ((long)SLK + (long)b*PVOX + pp) * CIN + c;
    *a = rtf32(*a / cntv);
}

// ---------------- tf32 mma.sync implicit-GEMM 3x3x3 conv ----------------------
// dz-sharing: per (dx,dy, ci-chunk) stage A band of 130 rows once, run the 3
// dz taps from smem row offsets 0/1/2. A band + tap-t0 B double-buffered via
// cp.async; taps t0+1/t0+2 B reloaded synchronously (wait_group 0 -- see R7
// post-mortem: wait_group drains OLDEST groups first, so waiting for "just the
// new B" with wait_group 1 is impossible while the s+1 prefetch is in flight).
#define AROWS 132                 // 130 used, pad
template<int CI, int STAGE>
__global__ void __launch_bounds__(256) k_tconv(const float* __restrict__ bias) {
    __shared__ __align__(16) float sA[2][AROWS*36];
    __shared__ __align__(16) float sB[2][128*36];

    const float* __restrict__ gin = (STAGE == 0) ? (d_gp0 + (long)SLK*CI)
                                                 : (d_gp1 + (long)SLK*CI);
    const float* __restrict__ wb  = (STAGE == 0) ? d_wb1 : d_wb2;
    float*       __restrict__ gout = (STAGE == 0) ? d_grid1 : d_grid2;

    int blk = blockIdx.x;                   // BB*NTILE
    int b = blk / NTILE, tile = blk % NTILE;
    long pbase = (long)b * PVOX + tile * 128;

    int tid = threadIdx.x, warp = tid >> 5, lane = tid & 31;
    int wm = warp & 3, wn = warp >> 2;
    uint32_t aA0 = smem_u32(sA[0]), aA1 = smem_u32(sA[1]);
    uint32_t aB0 = smem_u32(sB[0]), aB1 = smem_u32(sB[1]);

    float acc[2][8][4];
    #pragma unroll
    for (int mi = 0; mi < 2; mi++)
        #pragma unroll
        for (int ni = 0; ni < 8; ni++)
            #pragma unroll
            for (int j = 0; j < 4; j++) acc[mi][ni][j] = 0.f;

    int q = lane >> 2, rr = lane & 3;
    int aoffs = (wm*32 + q)*36 + rr;
    int boffs = (wn*64 + q)*36 + rr;

    const int NCK = CI / 32;
    const int NS = 9 * NCK;                 // stages: (dxdy, ck)

    // stage loader: band of 130 A rows + tap-t0 B rows for stage s into buf
    auto issue_stage = [&](int s, int buf) {
        int dxy = s / NCK, ck = s - (s / NCK) * NCK;
        int dxx = dxy / 3 - 1, dyy = dxy % 3 - 1;
        long astart = pbase + dxx * (PY*PZ) + dyy * PZ - 1;   // 130 rows
        const float* asrc = gin + astart * CI + ck * 32;
        uint32_t aA = buf ? aA1 : aA0;
        #pragma unroll
        for (int o2 = 0; o2 < 5; o2++) {
            int i = o2 * 256 + tid;
            if (i < 130*8) {
                int r = i >> 3, seg = i & 7;
                cpa16(aA + (uint32_t)(r*144 + seg*16), asrc + (long)r * CI + seg*4);
            }
        }
        int t0 = dxy * 3;                   // tap of dz=-1
        const float* bsrc = wb + (long)(t0 * COUT) * CI + ck * 32;
        uint32_t aB = buf ? aB1 : aB0;
        #pragma unroll
        for (int o2 = 0; o2 < 4; o2++) {
            int i = o2 * 256 + tid; int r = i >> 3, seg = i & 7;
            cpa16(aB + (uint32_t)(r*144 + seg*16), bsrc + (long)r * CI + seg*4);
        }
        asm volatile("cp.async.commit_group;");
    };

    issue_stage(0, 0);

    #pragma unroll 1
    for (int s = 0; s < NS; s++) {
        int buf = s & 1;
        if (s + 1 < NS) issue_stage(s + 1, buf ^ 1);
        // outstanding: [stage s (oldest, unless already drained), stage s+1]
        asm volatile("cp.async.wait_group %0;" :: "n"(1));
        __syncthreads();

        int dxy = s / NCK, ck = s - (s / NCK) * NCK;
        int t0 = dxy * 3;
        const uint32_t* sAu = (const uint32_t*)sA[buf];

        #pragma unroll 1
        for (int dz = 0; dz < 3; dz++) {
            const uint32_t* sBu;
            if (dz == 0) {
                sBu = (const uint32_t*)sB[buf];
            } else {
                // reload tap t0+dz into sB[buf] (tap t0 data consumed at dz=0)
                __syncthreads();
                const float* bsrc = wb + (long)((t0 + dz) * COUT) * CI + ck * 32;
                uint32_t aB = buf ? aB1 : aB0;
                #pragma unroll
                for (int o2 = 0; o2 < 4; o2++) {
                    int i = o2 * 256 + tid; int r = i >> 3, seg = i & 7;
                    cpa16(aB + (uint32_t)(r*144 + seg*16), bsrc + (long)r * CI + seg*4);
                }
                asm volatile("cp.async.commit_group;");
                // MUST be 0: wait_group drains oldest-first; the only way to
                // guarantee THIS B landed is to drain everything (the s+1
                // prefetch has had a full dz pass to arrive, so cost is low).
                asm volatile("cp.async.wait_group %0;" :: "n"(0));
                __syncthreads();
                sBu = (const uint32_t*)sB[buf];
            }
            int abase0 = aoffs + dz * 36;   // dz row shift within the band
            #pragma unroll
            for (int ks = 0; ks < 4; ks++) {
                int k0 = ks * 8;
                uint32_t b0[8], b1[8];
                #pragma unroll
                for (int ni = 0; ni < 8; ni++) {
                    int bbase = boffs + ni*8*36 + k0;
                    b0[ni] = sBu[bbase];
                    b1[ni] = sBu[bbase + 4];
                }
                #pragma unroll
                for (int mi = 0; mi < 2; mi++) {
                    int abase = abase0 + mi*16*36 + k0;
                    uint32_t a0 = sAu[abase];
                    uint32_t a1 = sAu[abase + 8*36];
                    uint32_t a2 = sAu[abase + 4];
                    uint32_t a3 = sAu[abase + 8*36 + 4];
                    #pragma unroll
                    for (int ni = 0; ni < 8; ni++)
                        mma_tf32(acc[mi][ni][0], acc[mi][ni][1], acc[mi][ni][2], acc[mi][ni][3],
                                 a0, a1, a2, a3, b0[ni], b1[ni]);
                }
            }
        }
        __syncthreads();
    }

    // epilogue: discard pad rows, add bias, store compact channels-last
    int cb = wn*64 + (lane & 3)*2;
    int prow = tile*128 + wm*32 + (lane >> 2);
    #pragma unroll
    for (int mi = 0; mi < 2; mi++) {
        int p0 = prow + mi*16;
        #pragma unroll
        for (int half = 0; half < 2; half++) {
            int pp = p0 + half*8;
            int zp = pp % PZ; int rem = pp / PZ; int yp = rem % PY; int xp = rem / PY;
            bool valid = (pp < PVOX) && (xp >= 1 && xp <= 32) && (yp >= 1 && yp <= 32)
                         && (zp >= 1 && zp <= 32);
            if (!valid) continue;
            long ob = ((long)b*NVOX + (((xp-1)*RES + (yp-1))*RES + (zp-1))) * COUT;
            #pragma unroll
            for (int ni = 0; ni < 8; ni++) {
                int col = cb + ni*8;
                float2 o2;
                o2.x = acc[mi][ni][half*2]   + bias[col];
                o2.y = acc[mi][ni][half*2+1] + bias[col+1];
                *(float2*)&gout[ob + col] = o2;
            }
        }
    }
}

// ---------------- GN1 stats + normalize+swish -> padded tf32 gp1 -------------
__global__ void k_gstats1() {
    int b = blockIdx.x >> 6, ch = blockIdx.x & 63;
    int c = threadIdx.x & 127, l2 = threadIdx.x >> 7;
    long base = ((long)b*NVOX + ch*512) * COUT;
    float s = 0.f, q = 0.f;
    for (int v = l2; v < 512; v += 2) {
        float x = d_grid1[base + (long)v*COUT + c];
        s += x; q += x*x;
    }
    __shared__ float ss[256], sq[256];
    ss[threadIdx.x] = s; sq[threadIdx.x] = q;
    __syncthreads();
    if (threadIdx.x < 8) {
        float S = 0.f, Q = 0.f;
        for (int j = 0; j < 16; j++) {
            int cc = threadIdx.x*16 + j;
            S += ss[cc] + ss[cc+128]; Q += sq[cc] + sq[cc+128];
        }
        atomicAdd(&d_gstats1[(b*8 + threadIdx.x)*2 + 0], S);
        atomicAdd(&d_gstats1[(b*8 + threadIdx.x)*2 + 1], Q);
    }
}

__global__ void k_gn1(const float* __restrict__ g, const float* __restrict__ bt) {
    long i = (long)blockIdx.x * 256 + threadIdx.x;
    int c = i & 127; int b = (int)(i >> 22);
    int v = (int)((i >> 7) & (NVOX-1));
    int gr = c >> 4;
    float S = d_gstats1[(b*8 + gr)*2], Q = d_gstats1[(b*8 + gr)*2 + 1];
    const float cnt = (float)NVOX * 16.f;
    float mu = S / cnt; float var = Q / cnt - mu*mu;
    float rs = rsqrtf(var + GEPS);
    float y = (d_grid1[i] - mu) * rs * g[c] + bt[c];
    float sw = y / (1.f + expf(-y));
    int x = v >> 10, yy = (v >> 5) & 31, z = v & 31;
    int pp = ((x+1)*PY + (yy+1))*PZ + (z+1);
    d_gp1[((long)SLK + (long)b*PVOX + pp)*COUT + c] = rtf32(sw);
}

// ---------------- GN2 per-channel stats ---------------------------------------
__global__ void k_cstats2() {
    int b = blockIdx.x >> 6, ch = blockIdx.x & 63;
    int c = threadIdx.x & 127, l2 = threadIdx.x >> 7;
    long base = ((long)b*NVOX + ch*512) * COUT;
    float s = 0.f, q = 0.f;
    for (int v = l2; v < 512; v += 2) {
        float x = d_grid2[base + (long)v*COUT + c];
        s += x; q += x*x;
    }
    __shared__ float ss[256], sq[256];
    ss[threadIdx.x] = s; sq[threadIdx.x] = q;
    __syncthreads();
    if (threadIdx.x < 128) {
        atomicAdd(&d_cstats2[(b*COUT + c)*2 + 0], ss[c] + ss[c+128]);
        atomicAdd(&d_cstats2[(b*COUT + c)*2 + 1], sq[c] + sq[c+128]);
    }
}

// ---------------- SE + fold GN2*SE into per-(b,c) affine ---------------------
__global__ void k_se(const float* __restrict__ w1, const float* __restrict__ b1,
                     const float* __restrict__ w2, const float* __restrict__ b2,
                     const float* __restrict__ gamma, const float* __restrict__ beta) {
    int b = blockIdx.x; int c = threadIdx.x;
    __shared__ float s[128], gmu[8], grs[8], s1[16];
    const float cnt = (float)NVOX;
    if (c < 8) {
        float S = 0.f, Q = 0.f;
        for (int j = 0; j < 16; j++) {
            S += d_cstats2[(b*COUT + c*16 + j)*2 + 0];
            Q += d_cstats2[(b*COUT + c*16 + j)*2 + 1];
        }
        float gc = cnt * 16.f;
        float mu = S / gc; float var = Q / gc - mu*mu;
        gmu[c] = mu; grs[c] = rsqrtf(var + GEPS);
    }
    __syncthreads();
    int gr = c >> 4;
    float mu = gmu[gr], rs = grs[gr];
    float csum = d_cstats2[(b*COUT + c)*2];
    s[c] = (csum / cnt - mu) * rs * gamma[c] + beta[c];
    __syncthreads();
    if (c < 16) {
        float a = b1[c];
        for (int j = 0; j < 128; j++) a += w1[c*128 + j] * s[j];
        s1[c] = fmaxf(a, 0.f);
    }
    __syncthreads();
    float a2 = b2[c];
    for (int j = 0; j < 16; j++) a2 += w2[c*16 + j] * s1[j];
    float se = 1.f / (1.f + expf(-a2));
    float rg = rs * gamma[c];
    d_A [b*COUT + c] = rg * se;
    d_Bc[b*COUT + c] = (beta[c] - mu * rg) * se;
}

// ---------------- point branch 1x1 conv + stats --------------------------------
__global__ void k_pt(const float* __restrict__ feat, const float* __restrict__ ptb) {
    int blk = blockIdx.x;
    int b = blk >> 10, n0 = (blk & 1023) * 32;
    __shared__ float fs[CIN*32];
    __shared__ float so[32*COUT];
    __shared__ float ss[256], sq[256];
    for (int e = threadIdx.x; e < CIN*32; e += 256) {
        int ci = e >> 5, nn = e & 31;
        fs[e] = feat[((long)(b*CIN) + ci)*NPTS + n0 + nn];
    }
    __syncthreads();
    int o = threadIdx.x & 127, h = threadIdx.x >> 7;
    float acc[16];
    float bv = ptb[o];
    #pragma unroll
    for (int j = 0; j < 16; j++) acc[j] = bv;
    for (int ci = 0; ci < CIN; ci++) {
        float w = d_ptw[ci*COUT + o];
        #pragma unroll
        for (int j = 0; j < 16; j++)
            acc[j] = fmaf(w, fs[ci*32 + h*16 + j], acc[j]);
    }
    float s = 0.f, q = 0.f;
    #pragma unroll
    for (int j = 0; j < 16; j++) {
        s += acc[j]; q += acc[j]*acc[j];
        so[(h*16 + j)*COUT + o] = acc[j];
    }
    ss[threadIdx.x] = s; sq[threadIdx.x] = q;
    __syncthreads();
    if (threadIdx.x < 8) {
        float S = 0.f, Q = 0.f;
        for (int j = 0; j < 16; j++) {
            int cc = threadIdx.x*16 + j;
            S += ss[cc] + ss[cc+128]; Q += sq[cc] + sq[cc+128];
        }
        atomicAdd(&d_ptstats[(b*8 + threadIdx.x)*2 + 0], S);
        atomicAdd(&d_ptstats[(b*8 + threadIdx.x)*2 + 1], Q);
    }
    for (int e = threadIdx.x; e < 32*COUT; e += 256) {
        int nn = e >> 7, oo = e & 127;
        d_pt[((long)(b*NPTS) + n0 + nn)*COUT + oo] = so[e];
    }
}

__global__ void k_ptab(const float* __restrict__ g, const float* __restrict__ bt) {
    int i = blockIdx.x * 256 + threadIdx.x;
    if (i >= BB*COUT) return;
    int b = i >> 7, c = i & 127, gr = c >> 4;
    const float cnt = 16.f * (float)NPTS;
    float S = d_ptstats[(b*8 + gr)*2], Q = d_ptstats[(b*8 + gr)*2 + 1];
    float mu = S / cnt, var = Q / cnt - mu*mu, rs = rsqrtf(var + GEPS);
    d_ptA[i] = rs * g[c];
    d_ptB[i] = bt[c] - mu * rs * g[c];
}

// ---------------- trilinear devoxelize + point add -> out (coalesced) ---------
__global__ void k_out(float* __restrict__ out) {
    __shared__ float so[64*132];
    int warp = threadIdx.x >> 5, lane = threadIdx.x & 31;
    int blk = blockIdx.x;
    int b = blk >> 9;
    int n0 = (blk & 511) * 64;

    #pragma unroll 1
    for (int pass = 0; pass < 8; pass++) {
        int pt = pass * 8 + warp;
        int n = n0 + pt;
        float nx = d_normc[(b*3+0)*NPTS + n];
        float ny = d_normc[(b*3+1)*NPTS + n];
        float nz = d_normc[(b*3+2)*NPTS + n];
        int lx = (int)floorf(nx); float fx = nx - (float)lx; int hx = min(lx+1, RES-1);
        int ly = (int)floorf(ny); float fy = ny - (float)ly; int hy = min(ly+1, RES-1);
        int lz = (int)floorf(nz); float fz = nz - (float)lz; int hz = min(lz+1, RES-1);

        float4 acc = make_float4(0.f, 0.f, 0.f, 0.f);
        float sumw = 0.f;
        const float4* gp = (const float4*)d_grid2;
        #pragma unroll
        for (int k = 0; k < 8; k++) {
            int dx = k >> 2, dy = (k >> 1) & 1, dz = k & 1;
            int ix = dx ? hx : lx, iy = dy ? hy : ly, iz = dz ? hz : lz;
            float w = (dx ? fx : 1.f - fx) * (dy ? fy : 1.f - fy) * (dz ? fz : 1.f - fz);
            long row = ((long)(b*NVOX) + (ix*RES + iy)*RES + iz) * (COUT/4);
            float4 v = gp[row + lane];
            acc.x += w*v.x; acc.y += w*v.y; acc.z += w*v.z; acc.w += w*v.w;
            sumw += w;
        }
        float4 a  = ((const float4*)d_A )[b*32 + lane];
        float4 bc = ((const float4*)d_Bc)[b*32 + lane];
        float4 gv;
        gv.x = acc.x*a.x + sumw*bc.x; gv.y = acc.y*a.y + sumw*bc.y;
        gv.z = acc.z*a.z + sumw*bc.z; gv.w = acc.w*a.w + sumw*bc.w;

        float4 pv = ((const float4*)d_pt)[((long)(b*NPTS) + n)*32 + lane];
        float4 pa = ((const float4*)d_ptA)[b*32 + lane];
        float4 pb = ((const float4*)d_ptB)[b*32 + lane];
        float y;
        y = pv.x*pa.x + pb.x; gv.x += y / (1.f + expf(-y));
        y = pv.y*pa.y + pb.y; gv.y += y / (1.f + expf(-y));
        y = pv.z*pa.z + pb.z; gv.z += y / (1.f + expf(-y));
        y = pv.w*pa.w + pb.w; gv.w += y / (1.f + expf(-y));

        ((float4*)(so + pt*132))[lane] = gv;
    }
    __syncthreads();
    for (int e = threadIdx.x; e < 64*128; e += 256) {
        int c = e >> 6, n = e & 63;
        out[((long)(b*COUT) + c)*NPTS + n0 + n] = so[n*132 + c];
    }
}

// ---------------- launch --------------------------------------------------------
extern "C" void kernel_launch(void* const* d_in, const int* in_sizes, int n_in,
                              void* d_out, int out_size) {
    const float* features = (const float*)d_in[0];
    const float* coords   = (const float*)d_in[1];
    const float* conv1_w  = (const float*)d_in[2];
    const float* conv1_b  = (const float*)d_in[3];
    const float* gn1_g    = (const float*)d_in[4];
    const float* gn1_b    = (const float*)d_in[5];
    const float* conv2_w  = (const float*)d_in[6];
    const float* conv2_b  = (const float*)d_in[7];
    const float* gn2_g    = (const float*)d_in[8];
    const float* gn2_b    = (const float*)d_in[9];
    const float* se_w1    = (const float*)d_in[10];
    const float* se_b1    = (const float*)d_in[11];
    const float* se_w2    = (const float*)d_in[12];
    const float* se_b2    = (const float*)d_in[13];
    const float* pt_w     = (const float*)d_in[14];
    const float* pt_b     = (const float*)d_in[15];
    const float* ptgn_g   = (const float*)d_in[16];
    const float* ptgn_b   = (const float*)d_in[17];
    float* out = (float*)d_out;

    const long GP1SZ = ((long)BB*PVOX + 2*SLK) * COUT;

    k_prep<<<(27*COUT*COUT + 255)/256, 256>>>(conv1_w, conv2_w, pt_w);
    k_zero<<<(int)(GP1SZ/256), 256>>>();
    k_mean1<<<BB*3*16, 256>>>(coords);
    k_scale1<<<BB*16, 256>>>(coords);
    k_norm<<<(BB*3*NPTS + 255)/256, 256>>>(coords);
    k_scatter<<<BB*NPTS/8, 256>>>(features);
    k_div<<<(BB*NVOX*CIN)/256, 256>>>();
    k_tconv<CIN,0><<<BB*NTILE, 256>>>(conv1_b);
    k_gstats1<<<BB*64, 256>>>();
    k_gn1<<<(BB*NVOX*COUT)/256, 256>>>(gn1_g, gn1_b);
    k_tconv<COUT,1><<<BB*NTILE, 256>>>(conv2_b);
    k_cstats2<<<BB*64, 256>>>();
    k_se<<<BB, 128>>>(se_w1, se_b1, se_w2, se_b2, gn2_g, gn2_b);
    k_pt<<<BB*(NPTS/32), 256>>>(features, pt_b);
    k_ptab<<<(BB*COUT + 255)/256, 256>>>(ptgn_g, ptgn_b);
    k_out<<<BB*NPTS/64, 256>>>(out);
}